// round 12
// baseline (speedup 1.0000x reference)
#include <cuda_runtime.h>
#include <cuda_fp16.h>
#include <cstdint>

#define NN 50000
#define NE 800000
#define DIM 256
#define GF 200
#define NG 512

// ---------------------------------------------------------------------------
// Scratch (__device__ globals; no allocations allowed)
// ---------------------------------------------------------------------------
__device__ __half g_hW[(size_t)NN * DIM];        // hW (fp16)
__device__ __half g_Rh[(size_t)NN * DIM];        // relu(h@Wr+br) (fp16)
__device__ __half g_Ah[2][(size_t)NN * DIM];     // h split hi (both branches)
__device__ __half g_Al[2][(size_t)NN * DIM];     // h split lo
__device__ __half g_Ch[(size_t)NN * DIM];        // h1 (fp16)
__device__ __half g_WtH[6 * DIM * DIM];          // transposed weights fp16
__device__ float g_T[2][NG * DIM];
__device__ float g_gsum[NG * GF];
// CSR scratch (both branches)
__device__ int g_deg[2][NN];
__device__ int g_rowptr[2][NN + 1];
__device__ int g_woff[2][NN];
__device__ int g_eidsrc[2][NE];

enum { M_HW = 0, M_RES = 1, M_RD = 2 };

__device__ __forceinline__ float relu_f(float x) { return x > 0.f ? x : 0.f; }

__device__ __forceinline__ uint32_t smem_u32(const void* p) {
    uint32_t a;
    asm("{ .reg .u64 t; cvta.to.shared.u64 t, %1; cvt.u32.u64 %0, t; }" : "=r"(a) : "l"(p));
    return a;
}
__device__ __forceinline__ uint32_t swz(uint32_t off) { return off ^ ((off >> 3) & 0x70); }
__device__ __forceinline__ void cpa16(uint32_t s, const void* g, int sz) {
    asm volatile("cp.async.cg.shared.global [%0], [%1], 16, %2;" :: "r"(s), "l"(g), "r"(sz) : "memory");
}
__device__ __forceinline__ void ldsm4(uint32_t* r, uint32_t addr) {
    asm volatile("ldmatrix.sync.aligned.m8n8.x4.shared.b16 {%0,%1,%2,%3}, [%4];"
        : "=r"(r[0]), "=r"(r[1]), "=r"(r[2]), "=r"(r[3]) : "r"(addr));
}
__device__ __forceinline__ void mma16816(float* c, const uint32_t* a, const uint32_t* b) {
    asm volatile("mma.sync.aligned.m16n8k16.row.col.f32.f16.f16.f32 "
        "{%0,%1,%2,%3}, {%4,%5,%6,%7}, {%8,%9}, {%0,%1,%2,%3};"
        : "+f"(c[0]), "+f"(c[1]), "+f"(c[2]), "+f"(c[3])
        : "r"(a[0]), "r"(a[1]), "r"(a[2]), "r"(a[3]), "r"(b[0]), "r"(b[1]));
}

// ---------------------------------------------------------------------------
// GEMM core: BM=128, BN=128, BK=64. 256 threads = 8 warps, warp tile 32x64.
// D = Ah*Bh (+ Al*Bh if USELO). Compile-time specialized per path.
// ---------------------------------------------------------------------------
static const int SM_A = 0;                 // 2buf x 2split x 16KB = 64KB
static const int SM_B = 65536;             // 2buf x 16KB = 32KB
static const int GEMM_SMEM = 98304;        // 96KB

template <int MODE, bool USELO>
__device__ __forceinline__ void gemm_core(
    const __half* __restrict__ Ah, const __half* __restrict__ Al,
    const __half* __restrict__ Bh,
    const float* __restrict__ bias, const int* __restrict__ gid,
    float* __restrict__ outF, __half* __restrict__ outH,
    int M, int rowBase, int colBase, char* smem_raw)
{
    uint32_t sb = smem_u32(smem_raw);
    const int t = threadIdx.x;
    const int lane = t & 31;
    const int wid = t >> 5;

    const int m0 = (wid & 3) * 32;
    const int n0 = (wid >> 2) * 64;

    const int ar = (lane & 7) + ((lane >> 3) & 1) * 8;
    const int ak = ((lane >> 4) & 1) * 8;
    const int br_ = (lane & 7) + ((lane >> 4) & 1) * 8;
    const int bk = ((lane >> 3) & 1) * 8;

    uint32_t aRel[2], bRel[4];
    #pragma unroll
    for (int mt = 0; mt < 2; mt++)
        aRel[mt] = swz((uint32_t)(m0 + mt * 16 + ar) * 128 + ak * 2);
    #pragma unroll
    for (int q = 0; q < 4; q++)
        bRel[q] = swz((uint32_t)(n0 + q * 16 + br_) * 128 + bk * 2);

    const __half* Asrc[2] = { Ah, Al };
    constexpr int nAiter = USELO ? 8 : 4;
    auto loadAB = [&](int c, int buf) {
        #pragma unroll
        for (int i = 0; i < nAiter; i++) {
            int idx = i * 256 + t;
            int split = USELO ? (idx >> 10) : 0;
            int w = idx & 1023;
            int row = w >> 3, seg = w & 7;
            int gr = rowBase + row;
            int ok = gr < M;
            uint32_t sa = sb + SM_A + buf * 32768 + split * 16384 + swz(row * 128 + seg * 16);
            const __half* gp = Asrc[split] + (size_t)(ok ? gr : 0) * 256 + c * 64 + seg * 8;
            cpa16(sa, gp, ok ? 16 : 0);
        }
        #pragma unroll
        for (int i = 0; i < 4; i++) {
            int idx = i * 256 + t;
            int row = idx >> 3, seg = idx & 7;
            uint32_t sa = sb + SM_B + buf * 16384 + swz(row * 128 + seg * 16);
            const __half* gp = Bh + (size_t)(colBase + row) * 256 + c * 64 + seg * 8;
            cpa16(sa, gp, 16);
        }
    };
    loadAB(0, 0);
    asm volatile("cp.async.commit_group;" ::: "memory");

    float acc[2][8][4] = {};

    #pragma unroll
    for (int c = 0; c < 4; c++) {
        if (c < 3) {
            loadAB(c + 1, (c + 1) & 1);
            asm volatile("cp.async.commit_group;" ::: "memory");
            asm volatile("cp.async.wait_group 1;" ::: "memory");
        } else {
            asm volatile("cp.async.wait_group 0;" ::: "memory");
        }
        __syncthreads();

        uint32_t aH = sb + SM_A + (c & 1) * 32768;
        uint32_t aL = aH + 16384;
        uint32_t bB = sb + SM_B + (c & 1) * 16384;

        #pragma unroll
        for (int kk2 = 0; kk2 < 128; kk2 += 32) {
            uint32_t ah[2][4], al[2][4], bh[4][4];
            #pragma unroll
            for (int mt = 0; mt < 2; mt++)
                ldsm4(ah[mt], aH + (aRel[mt] ^ kk2));
            #pragma unroll
            for (int q = 0; q < 4; q++)
                ldsm4(bh[q], bB + (bRel[q] ^ kk2));
            if (USELO) {
                #pragma unroll
                for (int mt = 0; mt < 2; mt++)
                    ldsm4(al[mt], aL + (aRel[mt] ^ kk2));
            }
            #pragma unroll
            for (int mt = 0; mt < 2; mt++)
                #pragma unroll
                for (int nt = 0; nt < 8; nt++)
                    mma16816(acc[mt][nt], ah[mt], &bh[nt >> 1][(nt & 1) * 2]);
            if (USELO) {
                #pragma unroll
                for (int mt = 0; mt < 2; mt++)
                    #pragma unroll
                    for (int nt = 0; nt < 8; nt++)
                        mma16816(acc[mt][nt], al[mt], &bh[nt >> 1][(nt & 1) * 2]);
            }
        }
        __syncthreads();
    }

    if (MODE != M_RD) {
        __half* stg = (__half*)smem_raw;
        #pragma unroll
        for (int mt = 0; mt < 2; mt++) {
            #pragma unroll
            for (int nt = 0; nt < 8; nt++) {
                int r = m0 + mt * 16 + (lane >> 2);
                int cc = n0 + nt * 8 + (lane & 3) * 2;
                *(__half2*)&stg[r * 136 + cc] =
                    __floats2half2_rn(acc[mt][nt][0], acc[mt][nt][1]);
                *(__half2*)&stg[(r + 8) * 136 + cc] =
                    __floats2half2_rn(acc[mt][nt][2], acc[mt][nt][3]);
            }
        }
        __syncthreads();
        const int cl = t & 127;
        const int col = colBase + cl;
        if (MODE == M_HW) {
            for (int row = t >> 7; row < 128; row += 2) {
                int gr = rowBase + row;
                if (gr >= M) break;
                outH[(size_t)gr * 256 + col] = stg[row * 136 + cl];
            }
        } else {
            const float bc = bias[col];
            for (int row = t >> 7; row < 128; row += 2) {
                int gr = rowBase + row;
                if (gr >= M) break;
                float f = relu_f(__half2float(stg[row * 136 + cl]) + bc);
                outH[(size_t)gr * 256 + col] = __float2half_rn(f);
            }
        }
    } else {
        float* stg = (float*)smem_raw;
        #pragma unroll
        for (int mt = 0; mt < 2; mt++) {
            #pragma unroll
            for (int nt = 0; nt < 8; nt++) {
                int r = m0 + mt * 16 + (lane >> 2);
                int cc = n0 + nt * 8 + (lane & 3) * 2;
                stg[r * 129 + cc]           = acc[mt][nt][0];
                stg[r * 129 + cc + 1]       = acc[mt][nt][1];
                stg[(r + 8) * 129 + cc]     = acc[mt][nt][2];
                stg[(r + 8) * 129 + cc + 1] = acc[mt][nt][3];
            }
        }
        __syncthreads();
        const int cl = t & 127;
        const int col = colBase + cl;
        int curg = -1;
        float s = 0.f;
        const float bc = bias[col];
        for (int row = t >> 7; row < 128; row += 2) {
            int gr = rowBase + row;
            if (gr >= M) break;
            float v = relu_f(stg[row * 129 + cl] + bc);
            int g = gid[gr];
            if (g != curg) {
                if (curg >= 0) atomicAdd(&outF[(size_t)curg * 256 + col], s);
                curg = g; s = 0.f;
            }
            s += v;
        }
        if (curg >= 0) atomicAdd(&outF[(size_t)curg * 256 + col], s);
    }
}

// Merged hW (2-term) + R (1-term) GEMM. grid (4, 391): x<2 -> HW, else RES.
__global__ __launch_bounds__(256, 2)
void gemm_hwres(const __half* __restrict__ Ah, const __half* __restrict__ Al,
                const __half* __restrict__ BW,     // [W slab ; Wr slab]
                const float* __restrict__ br,
                __half* __restrict__ hW, __half* __restrict__ Rh, int M)
{
    extern __shared__ char smem_raw[];
    int rowBase = blockIdx.y * 128;
    if (blockIdx.x < 2)
        gemm_core<M_HW, true>(Ah, Al, BW, nullptr, nullptr, nullptr, hW,
                              M, rowBase, blockIdx.x * 128, smem_raw);
    else
        gemm_core<M_RES, false>(Ah, nullptr, BW + 65536, br, nullptr, nullptr, Rh,
                                M, rowBase, (blockIdx.x - 2) * 128, smem_raw);
}

__global__ __launch_bounds__(256, 2)
void gemm_rd(const __half* __restrict__ Ch, const __half* __restrict__ BRi,
             const float* __restrict__ rbi, const int* __restrict__ gid,
             float* __restrict__ T, int M)
{
    extern __shared__ char smem_raw[];
    gemm_core<M_RD, false>(Ch, nullptr, BRi, rbi, gid, T, nullptr,
                           M, blockIdx.y * 128, blockIdx.x * 128, smem_raw);
}

// ---------------------------------------------------------------------------
// fp32 -> fp16 hi/lo split, both branches in one launch
// ---------------------------------------------------------------------------
__global__ __launch_bounds__(256)
void split2_k(const float4* __restrict__ in0, const float4* __restrict__ in1,
              uint2* __restrict__ H0, uint2* __restrict__ L0,
              uint2* __restrict__ H1, uint2* __restrict__ L1, int n4)
{
    int i = blockIdx.x * blockDim.x + threadIdx.x;
    const float4* in = in0; uint2* H = H0; uint2* L = L0;
    if (i >= n4) { i -= n4; if (i >= n4) return; in = in1; H = H1; L = L1; }
    float4 f = in[i];
    float xs[4] = { f.x, f.y, f.z, f.w };
    union { __half h[4]; uint2 u; } hh, ll;
    #pragma unroll
    for (int j = 0; j < 4; j++) {
        __half hi = __float2half_rn(xs[j]);
        __half lo = __float2half_rn(xs[j] - __half2float(hi));
        hh.h[j] = hi; ll.h[j] = lo;
    }
    H[i] = hh.u; L[i] = ll.u;
}

// All 6 weight transposes in one launch
__global__ __launch_bounds__(256)
void wsplit_all(const float* __restrict__ w0, const float* __restrict__ w1,
                const float* __restrict__ w2, const float* __restrict__ w3,
                const float* __restrict__ w4, const float* __restrict__ w5,
                __half* __restrict__ H)
{
    int idx = blockIdx.x * 256 + threadIdx.x;
    int m = idx >> 16;
    int rem = idx & 65535;
    int n = rem >> 8, k = rem & 255;
    const float* srcs[6] = { w0, w1, w2, w3, w4, w5 };
    H[idx] = __float2half_rn(srcs[m][k * DIM + n]);
}

// ---------------------------------------------------------------------------
// CSR build (both branches per launch)
// ---------------------------------------------------------------------------
__global__ void zero2_i(int* p0, int* p1, int n)
{
    int i = blockIdx.x * blockDim.x + threadIdx.x;
    if (i < n) p0[i] = 0;
    else if (i < 2 * n) p1[i - n] = 0;
}
__global__ __launch_bounds__(256)
void hist2_k(const int* __restrict__ d0, const int* __restrict__ d1,
             int* __restrict__ c0, int* __restrict__ c1, int n)
{
    int i = blockIdx.x * blockDim.x + threadIdx.x;
    if (i < n) atomicAdd(&c0[d0[i]], 1);
    else if (i < 2 * n) { i -= n; atomicAdd(&c1[d1[i]], 1); }
}
// 2-CTA full exclusive scan (one CTA per branch), shfl-based
__global__ __launch_bounds__(1024)
void scan2cta_k(const int* __restrict__ deg0, const int* __restrict__ deg1,
                int* __restrict__ rp0, int* __restrict__ rp1,
                int* __restrict__ wo0, int* __restrict__ wo1)
{
    const int b = blockIdx.x;
    const int* deg = b ? deg1 : deg0;
    int* rp = b ? rp1 : rp0;
    int* wo = b ? wo1 : wo0;
    __shared__ int wsum[32];
    __shared__ int woffs[32];
    __shared__ int carry;
    const int t = threadIdx.x;
    const int lane = t & 31, wd = t >> 5;
    if (t == 0) carry = 0;
    __syncthreads();
    for (int base = 0; base < NN; base += 1024) {
        int idx = base + t;
        int v = (idx < NN) ? deg[idx] : 0;
        // inclusive warp scan
        int x = v;
        #pragma unroll
        for (int off = 1; off < 32; off <<= 1) {
            int y = __shfl_up_sync(0xffffffffu, x, off);
            if (lane >= off) x += y;
        }
        if (lane == 31) wsum[wd] = x;
        __syncthreads();
        if (wd == 0) {
            int wv = wsum[lane];
            int wx = wv;
            #pragma unroll
            for (int off = 1; off < 32; off <<= 1) {
                int y = __shfl_up_sync(0xffffffffu, wx, off);
                if (lane >= off) wx += y;
            }
            woffs[lane] = wx - wv;
        }
        __syncthreads();
        int excl = x - v + woffs[wd] + carry;
        if (idx < NN) { rp[idx] = excl; wo[idx] = excl; }
        __syncthreads();
        if (t == 1023) carry += x + woffs[31];   // total of this chunk
        __syncthreads();
    }
    if (t == 0) rp[NN] = NE;
}
__global__ __launch_bounds__(256)
void fill2_k(const int* __restrict__ s0, const int* __restrict__ d0,
             const int* __restrict__ s1, const int* __restrict__ d1,
             int* __restrict__ w0, int* __restrict__ w1,
             int* __restrict__ e0, int* __restrict__ e1, int n)
{
    int i = blockIdx.x * blockDim.x + threadIdx.x;
    if (i < n) {
        int pos = atomicAdd(&w0[d0[i]], 1);
        e0[pos] = s0[i];
    } else if (i < 2 * n) {
        i -= n;
        int pos = atomicAdd(&w1[d1[i]], 1);
        e1[pos] = s1[i];
    }
}

// ---------------------------------------------------------------------------
// Fused gather + combine (fp16 hW): agg = sum_in hW; h1 = relu(agg+b) + R
// ---------------------------------------------------------------------------
__global__ __launch_bounds__(128)
void gather_combine_k(const __half2* __restrict__ hW2, const int* __restrict__ rowptr,
                      const int* __restrict__ eidsrc, const __half2* __restrict__ R2,
                      const float* __restrict__ bvec,
                      __half2* __restrict__ H2)
{
    int n = blockIdx.x;
    int t = threadIdx.x;
    int start = rowptr[n], end = rowptr[n + 1];
    float ax = 0.f, ay = 0.f, bx = 0.f, by = 0.f;
    int j = start;
    for (; j + 1 < end; j += 2) {
        int s0 = __ldg(eidsrc + j);
        int s1 = __ldg(eidsrc + j + 1);
        float2 v0 = __half22float2(hW2[(size_t)s0 * 128 + t]);
        float2 v1 = __half22float2(hW2[(size_t)s1 * 128 + t]);
        ax += v0.x; ay += v0.y;
        bx += v1.x; by += v1.y;
    }
    if (j < end) {
        int s0 = __ldg(eidsrc + j);
        float2 v0 = __half22float2(hW2[(size_t)s0 * 128 + t]);
        ax += v0.x; ay += v0.y;
    }
    ax += bx; ay += by;
    float2 bb = ((const float2*)bvec)[t];
    float2 r = __half22float2(R2[(size_t)n * 128 + t]);
    float v0 = relu_f(ax + bb.x) + r.x;
    float v1 = relu_f(ay + bb.y) + r.y;
    H2[(size_t)n * 128 + t] = __floats2half2_rn(v0, v1);
}

// zero gsum + T[0] + T[1] in one launch
__global__ void zero3_k(float4* a, int na, float4* b, int nb, float4* c, int nc)
{
    int i = blockIdx.x * blockDim.x + threadIdx.x;
    float4 z = make_float4(0.f, 0.f, 0.f, 0.f);
    if (i < na) a[i] = z;
    else if (i < na + nb) b[i - na] = z;
    else if (i < na + nb + nc) c[i - na - nb] = z;
}

// gsum[g,:GF] += T[g,:256] @ Ro[256,GF] + cnt(g)*rbo ; cnt via binary search
__global__ __launch_bounds__(256)
void readout_small(const float* __restrict__ T, const float* __restrict__ Ro,
                   const float* __restrict__ rbo, const int* __restrict__ gid,
                   float* __restrict__ gsum)
{
    __shared__ float sT[DIM];
    __shared__ int scnt;
    int g = blockIdx.x;
    int t = threadIdx.x;
    sT[t] = T[(size_t)g * DIM + t];
    if (t == 0) {
        int lo = 0, hi = NN;
        while (lo < hi) { int m = (lo + hi) >> 1; if (gid[m] < g) lo = m + 1; else hi = m; }
        int lo2 = lo, hi2 = NN;
        while (lo2 < hi2) { int m = (lo2 + hi2) >> 1; if (gid[m] <= g) lo2 = m + 1; else hi2 = m; }
        scnt = lo2 - lo;
    }
    __syncthreads();
    if (t < GF) {
        float a = 0.f;
        #pragma unroll 8
        for (int k = 0; k < DIM; k++) a += sT[k] * Ro[k * GF + t];
        gsum[(size_t)g * GF + t] += a + (float)scnt * rbo[t];
    }
}

__global__ __launch_bounds__(256)
void predict_k(const float* __restrict__ gsum, const float* __restrict__ Wp,
               const float* __restrict__ bp, float* __restrict__ out)
{
    int warp = (int)((blockIdx.x * (size_t)blockDim.x + threadIdx.x) >> 5);
    int lane = threadIdx.x & 31;
    if (warp >= NG) return;
    const float* row = gsum + (size_t)warp * GF;
    float s = 0.f;
    for (int f = lane; f < GF; f += 32) s += row[f] * Wp[f];
    #pragma unroll
    for (int o = 16; o; o >>= 1) s += __shfl_xor_sync(0xffffffffu, s, o);
    if (lane == 0) out[warp] = s + bp[0];
}

// ---------------------------------------------------------------------------
extern "C" void kernel_launch(void* const* d_in, const int* in_sizes, int n_in,
                              void* d_out, int out_size)
{
    const float* nf[2]  = { (const float*)d_in[0], (const float*)d_in[2] };
    const int*   src[2] = { (const int*)d_in[4],   (const int*)d_in[7] };
    const int*   dst[2] = { (const int*)d_in[5],   (const int*)d_in[8] };
    const int*   gid[2] = { (const int*)d_in[6],   (const int*)d_in[9] };
    const float* W[2]   = { (const float*)d_in[10], (const float*)d_in[14] };
    const float* b[2]   = { (const float*)d_in[11], (const float*)d_in[15] };
    const float* Wr[2]  = { (const float*)d_in[12], (const float*)d_in[16] };
    const float* br[2]  = { (const float*)d_in[13], (const float*)d_in[17] };
    const float* Ri[2]  = { (const float*)d_in[18], (const float*)d_in[22] };
    const float* rbi[2] = { (const float*)d_in[19], (const float*)d_in[23] };
    const float* Ro[2]  = { (const float*)d_in[20], (const float*)d_in[24] };
    const float* rbo[2] = { (const float*)d_in[21], (const float*)d_in[25] };
    const float* Wp = (const float*)d_in[26];
    const float* bp = (const float*)d_in[27];
    float* out = (float*)d_out;

    float *T, *gsum;
    __half *hWp, *Rhp, *Ahp, *Alp, *Chp, *WtH;
    int *deg, *rowptr, *woff, *eidsrc;
    cudaGetSymbolAddress((void**)&hWp, g_hW);
    cudaGetSymbolAddress((void**)&Rhp, g_Rh);
    cudaGetSymbolAddress((void**)&Ahp, g_Ah);
    cudaGetSymbolAddress((void**)&Alp, g_Al);
    cudaGetSymbolAddress((void**)&Chp, g_Ch);
    cudaGetSymbolAddress((void**)&WtH, g_WtH);
    cudaGetSymbolAddress((void**)&T, g_T);
    cudaGetSymbolAddress((void**)&gsum, g_gsum);
    cudaGetSymbolAddress((void**)&deg, g_deg);
    cudaGetSymbolAddress((void**)&rowptr, g_rowptr);
    cudaGetSymbolAddress((void**)&woff, g_woff);
    cudaGetSymbolAddress((void**)&eidsrc, g_eidsrc);

    const size_t ND = (size_t)NN * DIM;

    cudaFuncSetAttribute((const void*)gemm_hwres, cudaFuncAttributeMaxDynamicSharedMemorySize, GEMM_SMEM);
    cudaFuncSetAttribute((const void*)gemm_rd,    cudaFuncAttributeMaxDynamicSharedMemorySize, GEMM_SMEM);

    const int n4 = NN * DIM / 4;
    const dim3 gridHR(4, (NN + 127) / 128);  // merged hW+RES
    const dim3 gridRD(2, (NN + 127) / 128);

    // 1: weight transposes (fp16)
    wsplit_all<<<6 * 65536 / 256, 256>>>(W[0], Wr[0], Ri[0], W[1], Wr[1], Ri[1], WtH);
    // 2: zero gsum + T0 + T1
    {
        int na = NG * GF / 4, nb = NG * DIM / 4;
        zero3_k<<<(na + 2 * nb + 255) / 256, 256>>>((float4*)gsum, na,
                                                    (float4*)T, nb,
                                                    (float4*)(T + NG * DIM), nb);
    }
    // 3: split both h
    split2_k<<<(2 * n4 + 255) / 256, 256>>>((const float4*)nf[0], (const float4*)nf[1],
                                            (uint2*)Ahp, (uint2*)Alp,
                                            (uint2*)(Ahp + ND), (uint2*)(Alp + ND), n4);
    // 4: merged hW+R GEMM, branch 0   [ncu-profiled slot]
    gemm_hwres<<<gridHR, 256, GEMM_SMEM>>>(Ahp, Alp, WtH, br[0], hWp, Rhp, NN);
    // 5-8: CSR build for BOTH branches
    zero2_i<<<(2 * NN + 255) / 256, 256>>>(deg, deg + NN, NN);
    hist2_k<<<(2 * NE + 255) / 256, 256>>>(dst[0], dst[1], deg, deg + NN, NE);
    scan2cta_k<<<2, 1024>>>(deg, deg + NN, rowptr, rowptr + NN + 1, woff, woff + NN);
    fill2_k<<<(2 * NE + 255) / 256, 256>>>(src[0], dst[0], src[1], dst[1],
                                           woff, woff + NN, eidsrc, eidsrc + NE, NE);
    // 9: gather+combine branch 0
    gather_combine_k<<<NN, 128>>>((const __half2*)hWp, rowptr, eidsrc,
                                  (const __half2*)Rhp, b[0], (__half2*)Chp);
    // 10: readout GEMM branch 0
    gemm_rd<<<gridRD, 256, GEMM_SMEM>>>(Chp, WtH + (size_t)2 * 65536, rbi[0], gid[0], T, NN);
    // 11: small readout branch 0
    readout_small<<<NG, 256>>>(T, Ro[0], rbo[0], gid[0], gsum);
    // 12: merged hW+R GEMM branch 1
    gemm_hwres<<<gridHR, 256, GEMM_SMEM>>>(Ahp + ND, Alp + ND, WtH + (size_t)3 * 65536,
                                           br[1], hWp, Rhp, NN);
    // 13: gather+combine branch 1
    gather_combine_k<<<NN, 128>>>((const __half2*)hWp, rowptr + NN + 1, eidsrc + NE,
                                  (const __half2*)Rhp, b[1], (__half2*)Chp);
    // 14: readout GEMM branch 1
    gemm_rd<<<gridRD, 256, GEMM_SMEM>>>(Chp, WtH + (size_t)5 * 65536, rbi[1], gid[1],
                                        T + NG * DIM, NN);
    // 15: small readout branch 1
    readout_small<<<NG, 256>>>(T + NG * DIM, Ro[1], rbo[1], gid[1], gsum);
    // 16: predictor
    predict_k<<<(NG * 32 + 255) / 256, 256>>>(gsum, Wp, bp, out);
}

// round 13
// speedup vs baseline: 1.0806x; 1.0806x over previous
#include <cuda_runtime.h>
#include <cuda_fp16.h>
#include <cstdint>

#define NN 50000
#define NE 800000
#define DIM 256
#define GF 200
#define NG 512

// ---------------------------------------------------------------------------
// Scratch (__device__ globals; no allocations allowed)
// ---------------------------------------------------------------------------
__device__ __half g_hW[(size_t)NN * DIM];        // hW (fp16)
__device__ __half g_Rh[(size_t)NN * DIM];        // relu(h@Wr+br) (fp16)
__device__ __half g_Ah[2][(size_t)NN * DIM];     // h split hi (both branches)
__device__ __half g_Al[2][(size_t)NN * DIM];     // h split lo
__device__ __half g_Ch[(size_t)NN * DIM];        // h1 (fp16)
__device__ __half g_WtH[6 * DIM * DIM];          // transposed weights fp16
__device__ float g_T[2][NG * DIM];
__device__ float g_gsum[NG * GF];
// CSR scratch (both branches)
__device__ int g_deg[2][NN];
__device__ int g_part[2][NN];
__device__ int g_rowptr[2][NN + 1];
__device__ int g_woff[2][NN];
__device__ int g_bsum[2][64];
__device__ int g_eidsrc[2][NE];

enum { M_HW = 0, M_RES = 1, M_RD = 2 };

__device__ __forceinline__ float relu_f(float x) { return x > 0.f ? x : 0.f; }

__device__ __forceinline__ uint32_t smem_u32(const void* p) {
    uint32_t a;
    asm("{ .reg .u64 t; cvta.to.shared.u64 t, %1; cvt.u32.u64 %0, t; }" : "=r"(a) : "l"(p));
    return a;
}
__device__ __forceinline__ uint32_t swz(uint32_t off) { return off ^ ((off >> 3) & 0x70); }
__device__ __forceinline__ void cpa16(uint32_t s, const void* g, int sz) {
    asm volatile("cp.async.cg.shared.global [%0], [%1], 16, %2;" :: "r"(s), "l"(g), "r"(sz) : "memory");
}
__device__ __forceinline__ void ldsm4(uint32_t* r, uint32_t addr) {
    asm volatile("ldmatrix.sync.aligned.m8n8.x4.shared.b16 {%0,%1,%2,%3}, [%4];"
        : "=r"(r[0]), "=r"(r[1]), "=r"(r[2]), "=r"(r[3]) : "r"(addr));
}
__device__ __forceinline__ void mma16816(float* c, const uint32_t* a, const uint32_t* b) {
    asm volatile("mma.sync.aligned.m16n8k16.row.col.f32.f16.f16.f32 "
        "{%0,%1,%2,%3}, {%4,%5,%6,%7}, {%8,%9}, {%0,%1,%2,%3};"
        : "+f"(c[0]), "+f"(c[1]), "+f"(c[2]), "+f"(c[3])
        : "r"(a[0]), "r"(a[1]), "r"(a[2]), "r"(a[3]), "r"(b[0]), "r"(b[1]));
}

// ---------------------------------------------------------------------------
// HMMA GEMM: BM=128, BN=128, BK=64. 256 threads = 8 warps, warp tile 32x64.
// D = Ah*Bh (+ Al*Bh if USELO). Fully compile-time specialized.
// A/B smem double-buffered. 2 CTAs/SM (96KB smem, <=128 regs).
// ---------------------------------------------------------------------------
static const int SM_A = 0;                 // 2buf x 2split x 16KB = 64KB
static const int SM_B = 65536;             // 2buf x 16KB = 32KB
static const int GEMM_SMEM = 98304;        // 96KB

template <int MODE, bool USELO>
__global__ __launch_bounds__(256, 2)
void gemm_tc(const __half* __restrict__ Ah, const __half* __restrict__ Al,
             const __half* __restrict__ Bh,
             const float* __restrict__ bias,   // RES: br ; RD: rbi
             const int* __restrict__ gid,      // RD
             float* __restrict__ outF,         // RD: T
             __half* __restrict__ outH,        // HW: hW ; RES: R
             int M)
{
    extern __shared__ char smem_raw[];
    uint32_t sb = smem_u32(smem_raw);
    const int t = threadIdx.x;
    const int lane = t & 31;
    const int wid = t >> 5;
    const int rowBase = blockIdx.y * 128;
    const int colBase = blockIdx.x * 128;

    const int m0 = (wid & 3) * 32;
    const int n0 = (wid >> 2) * 64;

    const int ar = (lane & 7) + ((lane >> 3) & 1) * 8;
    const int ak = ((lane >> 4) & 1) * 8;
    const int br_ = (lane & 7) + ((lane >> 4) & 1) * 8;
    const int bk = ((lane >> 3) & 1) * 8;

    uint32_t aRel[2], bRel[4];
    #pragma unroll
    for (int mt = 0; mt < 2; mt++)
        aRel[mt] = swz((uint32_t)(m0 + mt * 16 + ar) * 128 + ak * 2);
    #pragma unroll
    for (int q = 0; q < 4; q++)
        bRel[q] = swz((uint32_t)(n0 + q * 16 + br_) * 128 + bk * 2);

    const __half* Asrc[2] = { Ah, Al };
    constexpr int nAiter = USELO ? 8 : 4;
    auto loadAB = [&](int c, int buf) {
        #pragma unroll
        for (int i = 0; i < nAiter; i++) {
            int idx = i * 256 + t;
            int split = USELO ? (idx >> 10) : 0;
            int w = idx & 1023;
            int row = w >> 3, seg = w & 7;
            int gr = rowBase + row;
            int ok = gr < M;
            uint32_t sa = sb + SM_A + buf * 32768 + split * 16384 + swz(row * 128 + seg * 16);
            const __half* gp = Asrc[split] + (size_t)(ok ? gr : 0) * 256 + c * 64 + seg * 8;
            cpa16(sa, gp, ok ? 16 : 0);
        }
        #pragma unroll
        for (int i = 0; i < 4; i++) {
            int idx = i * 256 + t;
            int row = idx >> 3, seg = idx & 7;
            uint32_t sa = sb + SM_B + buf * 16384 + swz(row * 128 + seg * 16);
            const __half* gp = Bh + (size_t)(colBase + row) * 256 + c * 64 + seg * 8;
            cpa16(sa, gp, 16);
        }
    };
    loadAB(0, 0);
    asm volatile("cp.async.commit_group;" ::: "memory");

    float acc[2][8][4] = {};

    #pragma unroll
    for (int c = 0; c < 4; c++) {
        if (c < 3) {
            loadAB(c + 1, (c + 1) & 1);
            asm volatile("cp.async.commit_group;" ::: "memory");
            asm volatile("cp.async.wait_group 1;" ::: "memory");
        } else {
            asm volatile("cp.async.wait_group 0;" ::: "memory");
        }
        __syncthreads();

        uint32_t aH = sb + SM_A + (c & 1) * 32768;
        uint32_t aL = aH + 16384;
        uint32_t bB = sb + SM_B + (c & 1) * 16384;

        #pragma unroll
        for (int kk2 = 0; kk2 < 128; kk2 += 32) {
            uint32_t ah[2][4], al[2][4], bh[4][4];
            #pragma unroll
            for (int mt = 0; mt < 2; mt++)
                ldsm4(ah[mt], aH + (aRel[mt] ^ kk2));
            #pragma unroll
            for (int q = 0; q < 4; q++)
                ldsm4(bh[q], bB + (bRel[q] ^ kk2));
            if (USELO) {
                #pragma unroll
                for (int mt = 0; mt < 2; mt++)
                    ldsm4(al[mt], aL + (aRel[mt] ^ kk2));
            }
            #pragma unroll
            for (int mt = 0; mt < 2; mt++)
                #pragma unroll
                for (int nt = 0; nt < 8; nt++)
                    mma16816(acc[mt][nt], ah[mt], &bh[nt >> 1][(nt & 1) * 2]);
            if (USELO) {
                #pragma unroll
                for (int mt = 0; mt < 2; mt++)
                    #pragma unroll
                    for (int nt = 0; nt < 8; nt++)
                        mma16816(acc[mt][nt], al[mt], &bh[nt >> 1][(nt & 1) * 2]);
            }
        }
        __syncthreads();
    }

    if (MODE != M_RD) {
        __half* stg = (__half*)smem_raw;
        #pragma unroll
        for (int mt = 0; mt < 2; mt++) {
            #pragma unroll
            for (int nt = 0; nt < 8; nt++) {
                int r = m0 + mt * 16 + (lane >> 2);
                int cc = n0 + nt * 8 + (lane & 3) * 2;
                *(__half2*)&stg[r * 136 + cc] =
                    __floats2half2_rn(acc[mt][nt][0], acc[mt][nt][1]);
                *(__half2*)&stg[(r + 8) * 136 + cc] =
                    __floats2half2_rn(acc[mt][nt][2], acc[mt][nt][3]);
            }
        }
        __syncthreads();
        const int cl = t & 127;
        const int col = colBase + cl;
        if (MODE == M_HW) {
            for (int row = t >> 7; row < 128; row += 2) {
                int gr = rowBase + row;
                if (gr >= M) break;
                outH[(size_t)gr * 256 + col] = stg[row * 136 + cl];
            }
        } else {  // M_RES
            const float bc = bias[col];
            for (int row = t >> 7; row < 128; row += 2) {
                int gr = rowBase + row;
                if (gr >= M) break;
                float f = relu_f(__half2float(stg[row * 136 + cl]) + bc);
                outH[(size_t)gr * 256 + col] = __float2half_rn(f);
            }
        }
    } else {
        float* stg = (float*)smem_raw;
        #pragma unroll
        for (int mt = 0; mt < 2; mt++) {
            #pragma unroll
            for (int nt = 0; nt < 8; nt++) {
                int r = m0 + mt * 16 + (lane >> 2);
                int cc = n0 + nt * 8 + (lane & 3) * 2;
                stg[r * 129 + cc]           = acc[mt][nt][0];
                stg[r * 129 + cc + 1]       = acc[mt][nt][1];
                stg[(r + 8) * 129 + cc]     = acc[mt][nt][2];
                stg[(r + 8) * 129 + cc + 1] = acc[mt][nt][3];
            }
        }
        __syncthreads();
        const int cl = t & 127;
        const int col = colBase + cl;
        int curg = -1;
        float s = 0.f;
        const float bc = bias[col];
        for (int row = t >> 7; row < 128; row += 2) {
            int gr = rowBase + row;
            if (gr >= M) break;
            float v = relu_f(stg[row * 129 + cl] + bc);
            int g = gid[gr];
            if (g != curg) {
                if (curg >= 0) atomicAdd(&outF[(size_t)curg * 256 + col], s);
                curg = g; s = 0.f;
            }
            s += v;
        }
        if (curg >= 0) atomicAdd(&outF[(size_t)curg * 256 + col], s);
    }
}

// ---------------------------------------------------------------------------
// fp32 -> fp16 hi/lo split, both branches in one launch
// ---------------------------------------------------------------------------
__global__ __launch_bounds__(256)
void split2_k(const float4* __restrict__ in0, const float4* __restrict__ in1,
              uint2* __restrict__ H0, uint2* __restrict__ L0,
              uint2* __restrict__ H1, uint2* __restrict__ L1, int n4)
{
    int i = blockIdx.x * blockDim.x + threadIdx.x;
    const float4* in = in0; uint2* H = H0; uint2* L = L0;
    if (i >= n4) { i -= n4; if (i >= n4) return; in = in1; H = H1; L = L1; }
    float4 f = in[i];
    float xs[4] = { f.x, f.y, f.z, f.w };
    union { __half h[4]; uint2 u; } hh, ll;
    #pragma unroll
    for (int j = 0; j < 4; j++) {
        __half hi = __float2half_rn(xs[j]);
        __half lo = __float2half_rn(xs[j] - __half2float(hi));
        hh.h[j] = hi; ll.h[j] = lo;
    }
    H[i] = hh.u; L[i] = ll.u;
}

// All 6 weight transposes in one launch
__global__ __launch_bounds__(256)
void wsplit_all(const float* __restrict__ w0, const float* __restrict__ w1,
                const float* __restrict__ w2, const float* __restrict__ w3,
                const float* __restrict__ w4, const float* __restrict__ w5,
                __half* __restrict__ H)
{
    int idx = blockIdx.x * 256 + threadIdx.x;
    int m = idx >> 16;
    int rem = idx & 65535;
    int n = rem >> 8, k = rem & 255;
    const float* srcs[6] = { w0, w1, w2, w3, w4, w5 };
    H[idx] = __float2half_rn(srcs[m][k * DIM + n]);
}

// ---------------------------------------------------------------------------
// CSR build — dual-branch, full parallelism
// ---------------------------------------------------------------------------
#define NB ((NN + 1023) / 1024)   // 49

__global__ void zero2_i(int* p0, int* p1, int n)
{
    int i = blockIdx.x * blockDim.x + threadIdx.x;
    if (i < n) p0[i] = 0;
    else if (i < 2 * n) p1[i - n] = 0;
}
__global__ __launch_bounds__(256)
void hist2_k(const int* __restrict__ d0, const int* __restrict__ d1,
             int* __restrict__ c0, int* __restrict__ c1, int n)
{
    int i = blockIdx.x * blockDim.x + threadIdx.x;
    if (i < n) atomicAdd(&c0[d0[i]], 1);
    else if (i < 2 * n) { i -= n; atomicAdd(&c1[d1[i]], 1); }
}
// grid 2*NB: block handles 1024 entries of one branch
__global__ __launch_bounds__(1024)
void scan1_k(const int* __restrict__ deg, int* __restrict__ part, int* __restrict__ bsum)
{
    __shared__ int s[1024];
    int b = blockIdx.x / NB;             // branch
    int blk = blockIdx.x % NB;
    const int* dg = deg + (size_t)b * NN;
    int* pt = part + (size_t)b * NN;
    int t = threadIdx.x;
    int idx = blk * 1024 + t;
    int v = (idx < NN) ? dg[idx] : 0;
    s[t] = v;
    __syncthreads();
    #pragma unroll
    for (int off = 1; off < 1024; off <<= 1) {
        int x = (t >= off) ? s[t - off] : 0;
        __syncthreads();
        s[t] += x;
        __syncthreads();
    }
    if (idx < NN) pt[idx] = s[t] - v;
    if (t == 1023) bsum[b * 64 + blk] = s[1023];
}
__global__ void scan2_k(int* bsum)
{
    int b = threadIdx.x;                 // 2 threads, one per branch
    if (b < 2) {
        int run = 0;
        for (int i = 0; i < NB; i++) { int v = bsum[b * 64 + i]; bsum[b * 64 + i] = run; run += v; }
    }
}
__global__ __launch_bounds__(1024)
void scan3_k(const int* __restrict__ part, const int* __restrict__ bsum,
             int* __restrict__ rowptr, int* __restrict__ woff)
{
    int b = blockIdx.x / NB;
    int blk = blockIdx.x % NB;
    int idx = blk * 1024 + threadIdx.x;
    const int* pt = part + (size_t)b * NN;
    int* rp = rowptr + (size_t)b * (NN + 1);
    int* wo = woff + (size_t)b * NN;
    if (idx < NN) {
        int r = pt[idx] + bsum[b * 64 + blk];
        rp[idx] = r;
        wo[idx] = r;
    }
    if (idx == 0) rp[NN] = NE;
}
__global__ __launch_bounds__(256)
void fill2_k(const int* __restrict__ s0, const int* __restrict__ d0,
             const int* __restrict__ s1, const int* __restrict__ d1,
             int* __restrict__ w0, int* __restrict__ w1,
             int* __restrict__ e0, int* __restrict__ e1, int n)
{
    int i = blockIdx.x * blockDim.x + threadIdx.x;
    if (i < n) {
        int pos = atomicAdd(&w0[d0[i]], 1);
        e0[pos] = s0[i];
    } else if (i < 2 * n) {
        i -= n;
        int pos = atomicAdd(&w1[d1[i]], 1);
        e1[pos] = s1[i];
    }
}

// ---------------------------------------------------------------------------
// Fused gather + combine (fp16 hW): agg = sum_in hW; h1 = relu(agg+b) + R
// ---------------------------------------------------------------------------
__global__ __launch_bounds__(128)
void gather_combine_k(const __half2* __restrict__ hW2, const int* __restrict__ rowptr,
                      const int* __restrict__ eidsrc, const __half2* __restrict__ R2,
                      const float* __restrict__ bvec,
                      __half2* __restrict__ H2)
{
    int n = blockIdx.x;
    int t = threadIdx.x;
    int start = rowptr[n], end = rowptr[n + 1];
    float ax = 0.f, ay = 0.f, bx = 0.f, by = 0.f;
    int j = start;
    for (; j + 1 < end; j += 2) {
        int s0 = __ldg(eidsrc + j);
        int s1 = __ldg(eidsrc + j + 1);
        float2 v0 = __half22float2(hW2[(size_t)s0 * 128 + t]);
        float2 v1 = __half22float2(hW2[(size_t)s1 * 128 + t]);
        ax += v0.x; ay += v0.y;
        bx += v1.x; by += v1.y;
    }
    if (j < end) {
        int s0 = __ldg(eidsrc + j);
        float2 v0 = __half22float2(hW2[(size_t)s0 * 128 + t]);
        ax += v0.x; ay += v0.y;
    }
    ax += bx; ay += by;
    float2 bb = ((const float2*)bvec)[t];
    float2 r = __half22float2(R2[(size_t)n * 128 + t]);
    float v0 = relu_f(ax + bb.x) + r.x;
    float v1 = relu_f(ay + bb.y) + r.y;
    H2[(size_t)n * 128 + t] = __floats2half2_rn(v0, v1);
}

// zero gsum + T[0] + T[1] in one launch
__global__ void zero3_k(float4* a, int na, float4* b, int nb, float4* c, int nc)
{
    int i = blockIdx.x * blockDim.x + threadIdx.x;
    float4 z = make_float4(0.f, 0.f, 0.f, 0.f);
    if (i < na) a[i] = z;
    else if (i < na + nb) b[i - na] = z;
    else if (i < na + nb + nc) c[i - na - nb] = z;
}

// gsum[g,:GF] += T[g,:256] @ Ro[256,GF] + cnt(g)*rbo ; cnt via binary search
__global__ __launch_bounds__(256)
void readout_small(const float* __restrict__ T, const float* __restrict__ Ro,
                   const float* __restrict__ rbo, const int* __restrict__ gid,
                   float* __restrict__ gsum)
{
    __shared__ float sT[DIM];
    __shared__ int scnt;
    int g = blockIdx.x;
    int t = threadIdx.x;
    sT[t] = T[(size_t)g * DIM + t];
    if (t == 0) {
        int lo = 0, hi = NN;
        while (lo < hi) { int m = (lo + hi) >> 1; if (gid[m] < g) lo = m + 1; else hi = m; }
        int lo2 = lo, hi2 = NN;
        while (lo2 < hi2) { int m = (lo2 + hi2) >> 1; if (gid[m] <= g) lo2 = m + 1; else hi2 = m; }
        scnt = lo2 - lo;
    }
    __syncthreads();
    if (t < GF) {
        float a = 0.f;
        #pragma unroll 8
        for (int k = 0; k < DIM; k++) a += sT[k] * Ro[k * GF + t];
        gsum[(size_t)g * GF + t] += a + (float)scnt * rbo[t];
    }
}

__global__ __launch_bounds__(256)
void predict_k(const float* __restrict__ gsum, const float* __restrict__ Wp,
               const float* __restrict__ bp, float* __restrict__ out)
{
    int warp = (int)((blockIdx.x * (size_t)blockDim.x + threadIdx.x) >> 5);
    int lane = threadIdx.x & 31;
    if (warp >= NG) return;
    const float* row = gsum + (size_t)warp * GF;
    float s = 0.f;
    for (int f = lane; f < GF; f += 32) s += row[f] * Wp[f];
    #pragma unroll
    for (int o = 16; o; o >>= 1) s += __shfl_xor_sync(0xffffffffu, s, o);
    if (lane == 0) out[warp] = s + bp[0];
}

// ---------------------------------------------------------------------------
extern "C" void kernel_launch(void* const* d_in, const int* in_sizes, int n_in,
                              void* d_out, int out_size)
{
    const float* nf[2]  = { (const float*)d_in[0], (const float*)d_in[2] };
    const int*   src[2] = { (const int*)d_in[4],   (const int*)d_in[7] };
    const int*   dst[2] = { (const int*)d_in[5],   (const int*)d_in[8] };
    const int*   gid[2] = { (const int*)d_in[6],   (const int*)d_in[9] };
    const float* W[2]   = { (const float*)d_in[10], (const float*)d_in[14] };
    const float* b[2]   = { (const float*)d_in[11], (const float*)d_in[15] };
    const float* Wr[2]  = { (const float*)d_in[12], (const float*)d_in[16] };
    const float* br[2]  = { (const float*)d_in[13], (const float*)d_in[17] };
    const float* Ri[2]  = { (const float*)d_in[18], (const float*)d_in[22] };
    const float* rbi[2] = { (const float*)d_in[19], (const float*)d_in[23] };
    const float* Ro[2]  = { (const float*)d_in[20], (const float*)d_in[24] };
    const float* rbo[2] = { (const float*)d_in[21], (const float*)d_in[25] };
    const float* Wp = (const float*)d_in[26];
    const float* bp = (const float*)d_in[27];
    float* out = (float*)d_out;

    float *T, *gsum;
    __half *hWp, *Rhp, *Ahp, *Alp, *Chp, *WtH;
    int *deg, *part, *rowptr, *woff, *bsum, *eidsrc;
    cudaGetSymbolAddress((void**)&hWp, g_hW);
    cudaGetSymbolAddress((void**)&Rhp, g_Rh);
    cudaGetSymbolAddress((void**)&Ahp, g_Ah);
    cudaGetSymbolAddress((void**)&Alp, g_Al);
    cudaGetSymbolAddress((void**)&Chp, g_Ch);
    cudaGetSymbolAddress((void**)&WtH, g_WtH);
    cudaGetSymbolAddress((void**)&T, g_T);
    cudaGetSymbolAddress((void**)&gsum, g_gsum);
    cudaGetSymbolAddress((void**)&deg, g_deg);
    cudaGetSymbolAddress((void**)&part, g_part);
    cudaGetSymbolAddress((void**)&rowptr, g_rowptr);
    cudaGetSymbolAddress((void**)&woff, g_woff);
    cudaGetSymbolAddress((void**)&bsum, g_bsum);
    cudaGetSymbolAddress((void**)&eidsrc, g_eidsrc);

    const size_t ND = (size_t)NN * DIM;

    cudaFuncSetAttribute((const void*)gemm_tc<M_HW,  true >, cudaFuncAttributeMaxDynamicSharedMemorySize, GEMM_SMEM);
    cudaFuncSetAttribute((const void*)gemm_tc<M_RES, false>, cudaFuncAttributeMaxDynamicSharedMemorySize, GEMM_SMEM);
    cudaFuncSetAttribute((const void*)gemm_tc<M_RD,  false>, cudaFuncAttributeMaxDynamicSharedMemorySize, GEMM_SMEM);

    const int n4 = NN * DIM / 4;
    const dim3 gridG(2, (NN + 127) / 128);

    // 1: weight transposes (fp16)
    wsplit_all<<<6 * 65536 / 256, 256>>>(W[0], Wr[0], Ri[0], W[1], Wr[1], Ri[1], WtH);
    // 2: zero gsum + T0 + T1
    {
        int na = NG * GF / 4, nb = NG * DIM / 4;
        zero3_k<<<(na + 2 * nb + 255) / 256, 256>>>((float4*)gsum, na,
                                                    (float4*)T, nb,
                                                    (float4*)(T + NG * DIM), nb);
    }
    // 3: split both h
    split2_k<<<(2 * n4 + 255) / 256, 256>>>((const float4*)nf[0], (const float4*)nf[1],
                                            (uint2*)Ahp, (uint2*)Alp,
                                            (uint2*)(Ahp + ND), (uint2*)(Alp + ND), n4);
    // 4: hW GEMM branch 0 (2-term)   [ncu-profiled slot]
    gemm_tc<M_HW, true><<<gridG, 256, GEMM_SMEM>>>(Ahp, Alp, WtH, nullptr, nullptr,
                                                   nullptr, hWp, NN);
    // 5: R GEMM branch 0 (1-term)
    gemm_tc<M_RES, false><<<gridG, 256, GEMM_SMEM>>>(Ahp, nullptr, WtH + 65536, br[0],
                                                     nullptr, nullptr, Rhp, NN);
    // 6-10: CSR build for BOTH branches (parallel dual-branch scan)
    zero2_i<<<(2 * NN + 255) / 256, 256>>>(deg, deg + NN, NN);
    hist2_k<<<(2 * NE + 255) / 256, 256>>>(dst[0], dst[1], deg, deg + NN, NE);
    scan1_k<<<2 * NB, 1024>>>(deg, part, bsum);
    scan2_k<<<1, 32>>>(bsum);
    scan3_k<<<2 * NB, 1024>>>(part, bsum, rowptr, woff);
    fill2_k<<<(2 * NE + 255) / 256, 256>>>(src[0], dst[0], src[1], dst[1],
                                           woff, woff + NN, eidsrc, eidsrc + NE, NE);
    // 11: gather+combine branch 0
    gather_combine_k<<<NN, 128>>>((const __half2*)hWp, rowptr, eidsrc,
                                  (const __half2*)Rhp, b[0], (__half2*)Chp);
    // 12: readout GEMM branch 0
    gemm_tc<M_RD, false><<<gridG, 256, GEMM_SMEM>>>(Chp, nullptr, WtH + (size_t)2 * 65536,
                                                    rbi[0], gid[0], T, nullptr, NN);
    // 13: small readout branch 0
    readout_small<<<NG, 256>>>(T, Ro[0], rbo[0], gid[0], gsum);
    // 14: hW GEMM branch 1
    gemm_tc<M_HW, true><<<gridG, 256, GEMM_SMEM>>>(Ahp + ND, Alp + ND,
                                                   WtH + (size_t)3 * 65536, nullptr,
                                                   nullptr, nullptr, hWp, NN);
    // 15: R GEMM branch 1
    gemm_tc<M_RES, false><<<gridG, 256, GEMM_SMEM>>>(Ahp + ND, nullptr,
                                                     WtH + (size_t)4 * 65536, br[1],
                                                     nullptr, nullptr, Rhp, NN);
    // 16: gather+combine branch 1
    gather_combine_k<<<NN, 128>>>((const __half2*)hWp, rowptr + NN + 1, eidsrc + NE,
                                  (const __half2*)Rhp, b[1], (__half2*)Chp);
    // 17: readout GEMM branch 1
    gemm_tc<M_RD, false><<<gridG, 256, GEMM_SMEM>>>(Chp, nullptr, WtH + (size_t)5 * 65536,
                                                    rbi[1], gid[1], T + NG * DIM, nullptr, NN);
    // 18: small readout branch 1
    readout_small<<<NG, 256>>>(T + NG * DIM, Ro[1], rbo[1], gid[1], gsum);
    // 19: predictor
    predict_k<<<(NG * 32 + 255) / 256, 256>>>(gsum, Wp, bp, out);
}

// round 14
// speedup vs baseline: 1.3890x; 1.2853x over previous
#include <cuda_runtime.h>
#include <cuda_fp16.h>
#include <cstdint>

#define NN 50000
#define NE 800000
#define DIM 256
#define GF 200
#define NG 512

// ---------------------------------------------------------------------------
// Scratch (__device__ globals; no allocations allowed)
// ---------------------------------------------------------------------------
__device__ __half g_hW[(size_t)NN * DIM];        // hW (fp16)
__device__ __half g_Rh[(size_t)NN * DIM];        // relu(h@Wr+br) (fp16)
__device__ __half g_Ah[2][(size_t)NN * DIM];     // h split hi (both branches)
__device__ __half g_Al[2][(size_t)NN * DIM];     // h split lo
__device__ __half g_Ch[(size_t)NN * DIM];        // h1 (fp16)
__device__ __half g_WtH[6 * DIM * DIM];          // transposed weights fp16
__device__ float g_snode[2][NN];                 // per-node readout scalars
__device__ float g_rowp[516];                    // [0:256) RoWp0, [256:512) RoWp1, 512/513 rbo.Wp
// CSR scratch (both branches)
__device__ int g_deg[2][NN];
__device__ int g_part[2][NN];
__device__ int g_rowptr[2][NN + 1];
__device__ int g_woff[2][NN];
__device__ int g_bsum[2][64];
__device__ int g_eidsrc[2][NE];

enum { M_HW = 0, M_RES = 1, M_RD = 2 };

__device__ __forceinline__ float relu_f(float x) { return x > 0.f ? x : 0.f; }

__device__ __forceinline__ uint32_t smem_u32(const void* p) {
    uint32_t a;
    asm("{ .reg .u64 t; cvta.to.shared.u64 t, %1; cvt.u32.u64 %0, t; }" : "=r"(a) : "l"(p));
    return a;
}
__device__ __forceinline__ uint32_t swz(uint32_t off) { return off ^ ((off >> 3) & 0x70); }
__device__ __forceinline__ void cpa16(uint32_t s, const void* g, int sz) {
    asm volatile("cp.async.cg.shared.global [%0], [%1], 16, %2;" :: "r"(s), "l"(g), "r"(sz) : "memory");
}
__device__ __forceinline__ void ldsm4(uint32_t* r, uint32_t addr) {
    asm volatile("ldmatrix.sync.aligned.m8n8.x4.shared.b16 {%0,%1,%2,%3}, [%4];"
        : "=r"(r[0]), "=r"(r[1]), "=r"(r[2]), "=r"(r[3]) : "r"(addr));
}
__device__ __forceinline__ void mma16816(float* c, const uint32_t* a, const uint32_t* b) {
    asm volatile("mma.sync.aligned.m16n8k16.row.col.f32.f16.f16.f32 "
        "{%0,%1,%2,%3}, {%4,%5,%6,%7}, {%8,%9}, {%0,%1,%2,%3};"
        : "+f"(c[0]), "+f"(c[1]), "+f"(c[2]), "+f"(c[3])
        : "r"(a[0]), "r"(a[1]), "r"(a[2]), "r"(a[3]), "r"(b[0]), "r"(b[1]));
}

// ---------------------------------------------------------------------------
// HMMA GEMM: BM=128, BN=128, BK=64. 256 threads = 8 warps, warp tile 32x64.
// D = Ah*Bh (+ Al*Bh if USELO). RD epilogue reduces rows to scalars via RoWp.
// ---------------------------------------------------------------------------
static const int SM_A = 0;                 // 2buf x 2split x 16KB = 64KB
static const int SM_B = 65536;             // 2buf x 16KB = 32KB
static const int SM_BW = 90112;            // bias/rowp slices (RD epilogue)
static const int GEMM_SMEM = 98304;        // 96KB

template <int MODE, bool USELO>
__global__ __launch_bounds__(256, 2)
void gemm_tc(const __half* __restrict__ Ah, const __half* __restrict__ Al,
             const __half* __restrict__ Bh,
             const float* __restrict__ bias,   // RES: br ; RD: rbi
             const float* __restrict__ rowp,   // RD: RoWp slab
             float* __restrict__ snode,        // RD
             __half* __restrict__ outH,        // HW: hW ; RES: R
             int M)
{
    extern __shared__ char smem_raw[];
    uint32_t sb = smem_u32(smem_raw);
    const int t = threadIdx.x;
    const int lane = t & 31;
    const int wid = t >> 5;
    const int rowBase = blockIdx.y * 128;
    const int colBase = blockIdx.x * 128;

    const int m0 = (wid & 3) * 32;
    const int n0 = (wid >> 2) * 64;

    const int ar = (lane & 7) + ((lane >> 3) & 1) * 8;
    const int ak = ((lane >> 4) & 1) * 8;
    const int br_ = (lane & 7) + ((lane >> 4) & 1) * 8;
    const int bk = ((lane >> 3) & 1) * 8;

    uint32_t aRel[2], bRel[4];
    #pragma unroll
    for (int mt = 0; mt < 2; mt++)
        aRel[mt] = swz((uint32_t)(m0 + mt * 16 + ar) * 128 + ak * 2);
    #pragma unroll
    for (int q = 0; q < 4; q++)
        bRel[q] = swz((uint32_t)(n0 + q * 16 + br_) * 128 + bk * 2);

    const __half* Asrc[2] = { Ah, Al };
    constexpr int nAiter = USELO ? 8 : 4;
    auto loadAB = [&](int c, int buf) {
        #pragma unroll
        for (int i = 0; i < nAiter; i++) {
            int idx = i * 256 + t;
            int split = USELO ? (idx >> 10) : 0;
            int w = idx & 1023;
            int row = w >> 3, seg = w & 7;
            int gr = rowBase + row;
            int ok = gr < M;
            uint32_t sa = sb + SM_A + buf * 32768 + split * 16384 + swz(row * 128 + seg * 16);
            const __half* gp = Asrc[split] + (size_t)(ok ? gr : 0) * 256 + c * 64 + seg * 8;
            cpa16(sa, gp, ok ? 16 : 0);
        }
        #pragma unroll
        for (int i = 0; i < 4; i++) {
            int idx = i * 256 + t;
            int row = idx >> 3, seg = idx & 7;
            uint32_t sa = sb + SM_B + buf * 16384 + swz(row * 128 + seg * 16);
            const __half* gp = Bh + (size_t)(colBase + row) * 256 + c * 64 + seg * 8;
            cpa16(sa, gp, 16);
        }
    };
    loadAB(0, 0);
    asm volatile("cp.async.commit_group;" ::: "memory");

    float acc[2][8][4] = {};

    #pragma unroll
    for (int c = 0; c < 4; c++) {
        if (c < 3) {
            loadAB(c + 1, (c + 1) & 1);
            asm volatile("cp.async.commit_group;" ::: "memory");
            asm volatile("cp.async.wait_group 1;" ::: "memory");
        } else {
            asm volatile("cp.async.wait_group 0;" ::: "memory");
        }
        __syncthreads();

        uint32_t aH = sb + SM_A + (c & 1) * 32768;
        uint32_t aL = aH + 16384;
        uint32_t bB = sb + SM_B + (c & 1) * 16384;

        #pragma unroll
        for (int kk2 = 0; kk2 < 128; kk2 += 32) {
            uint32_t ah[2][4], al[2][4], bh[4][4];
            #pragma unroll
            for (int mt = 0; mt < 2; mt++)
                ldsm4(ah[mt], aH + (aRel[mt] ^ kk2));
            #pragma unroll
            for (int q = 0; q < 4; q++)
                ldsm4(bh[q], bB + (bRel[q] ^ kk2));
            if (USELO) {
                #pragma unroll
                for (int mt = 0; mt < 2; mt++)
                    ldsm4(al[mt], aL + (aRel[mt] ^ kk2));
            }
            #pragma unroll
            for (int mt = 0; mt < 2; mt++)
                #pragma unroll
                for (int nt = 0; nt < 8; nt++)
                    mma16816(acc[mt][nt], ah[mt], &bh[nt >> 1][(nt & 1) * 2]);
            if (USELO) {
                #pragma unroll
                for (int mt = 0; mt < 2; mt++)
                    #pragma unroll
                    for (int nt = 0; nt < 8; nt++)
                        mma16816(acc[mt][nt], al[mt], &bh[nt >> 1][(nt & 1) * 2]);
            }
        }
        __syncthreads();
    }

    if (MODE != M_RD) {
        __half* stg = (__half*)smem_raw;
        #pragma unroll
        for (int mt = 0; mt < 2; mt++) {
            #pragma unroll
            for (int nt = 0; nt < 8; nt++) {
                int r = m0 + mt * 16 + (lane >> 2);
                int cc = n0 + nt * 8 + (lane & 3) * 2;
                *(__half2*)&stg[r * 136 + cc] =
                    __floats2half2_rn(acc[mt][nt][0], acc[mt][nt][1]);
                *(__half2*)&stg[(r + 8) * 136 + cc] =
                    __floats2half2_rn(acc[mt][nt][2], acc[mt][nt][3]);
            }
        }
        __syncthreads();
        const int cl = t & 127;
        const int col = colBase + cl;
        if (MODE == M_HW) {
            for (int row = t >> 7; row < 128; row += 2) {
                int gr = rowBase + row;
                if (gr >= M) break;
                outH[(size_t)gr * 256 + col] = stg[row * 136 + cl];
            }
        } else {  // M_RES
            const float bc = bias[col];
            for (int row = t >> 7; row < 128; row += 2) {
                int gr = rowBase + row;
                if (gr >= M) break;
                float f = relu_f(__half2float(stg[row * 136 + cl]) + bc);
                outH[(size_t)gr * 256 + col] = __float2half_rn(f);
            }
        }
    } else {
        // RD: reduce each node row to a scalar: s = sum_c relu(t+rbi)*RoWp
        float* stg = (float*)smem_raw;
        float* sB = (float*)(smem_raw + SM_BW);        // rbi slice [128]
        float* sW = sB + 128;                          // RoWp slice [128]
        if (t < 128) sB[t] = bias[colBase + t];
        else sW[t - 128] = rowp[colBase + (t - 128)];
        #pragma unroll
        for (int mt = 0; mt < 2; mt++) {
            #pragma unroll
            for (int nt = 0; nt < 8; nt++) {
                int r = m0 + mt * 16 + (lane >> 2);
                int cc = n0 + nt * 8 + (lane & 3) * 2;
                stg[r * 129 + cc]           = acc[mt][nt][0];
                stg[r * 129 + cc + 1]       = acc[mt][nt][1];
                stg[(r + 8) * 129 + cc]     = acc[mt][nt][2];
                stg[(r + 8) * 129 + cc + 1] = acc[mt][nt][3];
            }
        }
        __syncthreads();
        const int row = t & 127;
        const int half = t >> 7;
        const int gr = rowBase + row;
        if (gr < M) {
            float s = 0.f;
            const int c0 = half * 64;
            #pragma unroll 8
            for (int c = c0; c < c0 + 64; c++)
                s += relu_f(stg[row * 129 + c] + sB[c]) * sW[c];
            atomicAdd(&snode[gr], s);
        }
    }
}

// ---------------------------------------------------------------------------
// fp32 -> fp16 hi/lo split, both branches in one launch
// ---------------------------------------------------------------------------
__global__ __launch_bounds__(256)
void split2_k(const float4* __restrict__ in0, const float4* __restrict__ in1,
              uint2* __restrict__ H0, uint2* __restrict__ L0,
              uint2* __restrict__ H1, uint2* __restrict__ L1, int n4)
{
    int i = blockIdx.x * blockDim.x + threadIdx.x;
    const float4* in = in0; uint2* H = H0; uint2* L = L0;
    if (i >= n4) { i -= n4; if (i >= n4) return; in = in1; H = H1; L = L1; }
    float4 f = in[i];
    float xs[4] = { f.x, f.y, f.z, f.w };
    union { __half h[4]; uint2 u; } hh, ll;
    #pragma unroll
    for (int j = 0; j < 4; j++) {
        __half hi = __float2half_rn(xs[j]);
        __half lo = __float2half_rn(xs[j] - __half2float(hi));
        hh.h[j] = hi; ll.h[j] = lo;
    }
    H[i] = hh.u; L[i] = ll.u;
}

// All 6 weight transposes in one launch
__global__ __launch_bounds__(256)
void wsplit_all(const float* __restrict__ w0, const float* __restrict__ w1,
                const float* __restrict__ w2, const float* __restrict__ w3,
                const float* __restrict__ w4, const float* __restrict__ w5,
                __half* __restrict__ H)
{
    int idx = blockIdx.x * 256 + threadIdx.x;
    int m = idx >> 16;
    int rem = idx & 65535;
    int n = rem >> 8, k = rem & 255;
    const float* srcs[6] = { w0, w1, w2, w3, w4, w5 };
    H[idx] = __float2half_rn(srcs[m][k * DIM + n]);
}

// prep: zero snode (2*NN) + compute RoWp slabs + rbo.Wp scalars
__global__ __launch_bounds__(256)
void prep_zero_k(const float* __restrict__ Ro0, const float* __restrict__ Ro1,
                 const float* __restrict__ rbo0, const float* __restrict__ rbo1,
                 const float* __restrict__ Wp,
                 float* __restrict__ rowp, float* __restrict__ snode)
{
    int i = blockIdx.x * blockDim.x + threadIdx.x;
    if (i < 2 * NN) snode[i] = 0.f;
    if (i < 512) {
        const float* Ro = (i < 256) ? Ro0 : Ro1;
        int c = i & 255;
        float s = 0.f;
        for (int f = 0; f < GF; f++) s += Ro[c * GF + f] * Wp[f];
        rowp[i] = s;
    } else if (i == 512 || i == 513) {
        const float* rbo = (i == 512) ? rbo0 : rbo1;
        float s = 0.f;
        for (int f = 0; f < GF; f++) s += rbo[f] * Wp[f];
        rowp[i] = s;
    }
}

// ---------------------------------------------------------------------------
// CSR build — dual-branch, full parallelism
// ---------------------------------------------------------------------------
#define NB ((NN + 1023) / 1024)   // 49

__global__ void zero2_i(int* p0, int* p1, int n)
{
    int i = blockIdx.x * blockDim.x + threadIdx.x;
    if (i < n) p0[i] = 0;
    else if (i < 2 * n) p1[i - n] = 0;
}
__global__ __launch_bounds__(256)
void hist2_k(const int* __restrict__ d0, const int* __restrict__ d1,
             int* __restrict__ c0, int* __restrict__ c1, int n)
{
    int i = blockIdx.x * blockDim.x + threadIdx.x;
    if (i < n) atomicAdd(&c0[d0[i]], 1);
    else if (i < 2 * n) { i -= n; atomicAdd(&c1[d1[i]], 1); }
}
__global__ __launch_bounds__(1024)
void scan1_k(const int* __restrict__ deg, int* __restrict__ part, int* __restrict__ bsum)
{
    __shared__ int s[1024];
    int b = blockIdx.x / NB;
    int blk = blockIdx.x % NB;
    const int* dg = deg + (size_t)b * NN;
    int* pt = part + (size_t)b * NN;
    int t = threadIdx.x;
    int idx = blk * 1024 + t;
    int v = (idx < NN) ? dg[idx] : 0;
    s[t] = v;
    __syncthreads();
    #pragma unroll
    for (int off = 1; off < 1024; off <<= 1) {
        int x = (t >= off) ? s[t - off] : 0;
        __syncthreads();
        s[t] += x;
        __syncthreads();
    }
    if (idx < NN) pt[idx] = s[t] - v;
    if (t == 1023) bsum[b * 64 + blk] = s[1023];
}
__global__ void scan2_k(int* bsum)
{
    int b = threadIdx.x;
    if (b < 2) {
        int run = 0;
        for (int i = 0; i < NB; i++) { int v = bsum[b * 64 + i]; bsum[b * 64 + i] = run; run += v; }
    }
}
__global__ __launch_bounds__(1024)
void scan3_k(const int* __restrict__ part, const int* __restrict__ bsum,
             int* __restrict__ rowptr, int* __restrict__ woff)
{
    int b = blockIdx.x / NB;
    int blk = blockIdx.x % NB;
    int idx = blk * 1024 + threadIdx.x;
    const int* pt = part + (size_t)b * NN;
    int* rp = rowptr + (size_t)b * (NN + 1);
    int* wo = woff + (size_t)b * NN;
    if (idx < NN) {
        int r = pt[idx] + bsum[b * 64 + blk];
        rp[idx] = r;
        wo[idx] = r;
    }
    if (idx == 0) rp[NN] = NE;
}
__global__ __launch_bounds__(256)
void fill2_k(const int* __restrict__ s0, const int* __restrict__ d0,
             const int* __restrict__ s1, const int* __restrict__ d1,
             int* __restrict__ w0, int* __restrict__ w1,
             int* __restrict__ e0, int* __restrict__ e1, int n)
{
    int i = blockIdx.x * blockDim.x + threadIdx.x;
    if (i < n) {
        int pos = atomicAdd(&w0[d0[i]], 1);
        e0[pos] = s0[i];
    } else if (i < 2 * n) {
        i -= n;
        int pos = atomicAdd(&w1[d1[i]], 1);
        e1[pos] = s1[i];
    }
}

// ---------------------------------------------------------------------------
// Fused gather + combine: warp per node, uint4 (8 halfs) per lane.
// agg = sum_in hW; h1 = relu(agg+b) + R -> Ch fp16
// ---------------------------------------------------------------------------
__global__ __launch_bounds__(128)
void gather_combine_k(const uint4* __restrict__ hw4, const int* __restrict__ rowptr,
                      const int* __restrict__ eidsrc, const uint4* __restrict__ R4,
                      const float* __restrict__ bvec, uint4* __restrict__ Ch4)
{
    int node = blockIdx.x * 4 + (threadIdx.x >> 5);
    int lane = threadIdx.x & 31;
    int start = rowptr[node], end = rowptr[node + 1];
    float a[8] = {};
    int j = start;
    for (; j + 1 < end; j += 2) {
        int s0 = __ldg(eidsrc + j);
        int s1 = __ldg(eidsrc + j + 1);
        uint4 v0 = __ldg(hw4 + (size_t)s0 * 32 + lane);
        uint4 v1 = __ldg(hw4 + (size_t)s1 * 32 + lane);
        float2 f;
        f = __half22float2(*(__half2*)&v0.x); a[0] += f.x; a[1] += f.y;
        f = __half22float2(*(__half2*)&v0.y); a[2] += f.x; a[3] += f.y;
        f = __half22float2(*(__half2*)&v0.z); a[4] += f.x; a[5] += f.y;
        f = __half22float2(*(__half2*)&v0.w); a[6] += f.x; a[7] += f.y;
        f = __half22float2(*(__half2*)&v1.x); a[0] += f.x; a[1] += f.y;
        f = __half22float2(*(__half2*)&v1.y); a[2] += f.x; a[3] += f.y;
        f = __half22float2(*(__half2*)&v1.z); a[4] += f.x; a[5] += f.y;
        f = __half22float2(*(__half2*)&v1.w); a[6] += f.x; a[7] += f.y;
    }
    if (j < end) {
        int s0 = __ldg(eidsrc + j);
        uint4 v0 = __ldg(hw4 + (size_t)s0 * 32 + lane);
        float2 f;
        f = __half22float2(*(__half2*)&v0.x); a[0] += f.x; a[1] += f.y;
        f = __half22float2(*(__half2*)&v0.y); a[2] += f.x; a[3] += f.y;
        f = __half22float2(*(__half2*)&v0.z); a[4] += f.x; a[5] += f.y;
        f = __half22float2(*(__half2*)&v0.w); a[6] += f.x; a[7] += f.y;
    }
    uint4 rv = __ldg(R4 + (size_t)node * 32 + lane);
    const float4* b4 = (const float4*)bvec;
    float4 bb0 = b4[lane * 2], bb1 = b4[lane * 2 + 1];
    float2 r0 = __half22float2(*(__half2*)&rv.x);
    float2 r1 = __half22float2(*(__half2*)&rv.y);
    float2 r2 = __half22float2(*(__half2*)&rv.z);
    float2 r3 = __half22float2(*(__half2*)&rv.w);
    float v0 = relu_f(a[0] + bb0.x) + r0.x;
    float v1 = relu_f(a[1] + bb0.y) + r0.y;
    float v2 = relu_f(a[2] + bb0.z) + r1.x;
    float v3 = relu_f(a[3] + bb0.w) + r1.y;
    float v4 = relu_f(a[4] + bb1.x) + r2.x;
    float v5 = relu_f(a[5] + bb1.y) + r2.y;
    float v6 = relu_f(a[6] + bb1.z) + r3.x;
    float v7 = relu_f(a[7] + bb1.w) + r3.y;
    uint4 o;
    *(__half2*)&o.x = __floats2half2_rn(v0, v1);
    *(__half2*)&o.y = __floats2half2_rn(v2, v3);
    *(__half2*)&o.z = __floats2half2_rn(v4, v5);
    *(__half2*)&o.w = __floats2half2_rn(v6, v7);
    Ch4[(size_t)node * 32 + lane] = o;
}

// final: out[g] = segsum(snode0) + segsum(snode1) + cnt0*rbowp0 + cnt1*rbowp1 + bp
__global__ __launch_bounds__(256)
void final_k(const float* __restrict__ snode, const int* __restrict__ gid0,
             const int* __restrict__ gid1, const float* __restrict__ rowp,
             const float* __restrict__ bp, float* __restrict__ out)
{
    int warp = (int)((blockIdx.x * (size_t)blockDim.x + threadIdx.x) >> 5);
    int lane = threadIdx.x & 31;
    if (warp >= NG) return;
    int g = warp;
    float tot = 0.f;
    float bias = bp[0];
    #pragma unroll
    for (int k = 0; k < 2; k++) {
        const int* gid = k ? gid1 : gid0;
        const float* sn = snode + (size_t)k * NN;
        int lo = 0, hi = NN;
        while (lo < hi) { int m = (lo + hi) >> 1; if (gid[m] < g) lo = m + 1; else hi = m; }
        int lo2 = lo, hi2 = NN;
        while (lo2 < hi2) { int m = (lo2 + hi2) >> 1; if (gid[m] <= g) lo2 = m + 1; else hi2 = m; }
        bias += (float)(lo2 - lo) * rowp[512 + k];
        float s = 0.f;
        for (int i = lo + lane; i < lo2; i += 32) s += sn[i];
        tot += s;
    }
    #pragma unroll
    for (int o = 16; o; o >>= 1) tot += __shfl_xor_sync(0xffffffffu, tot, o);
    if (lane == 0) out[g] = tot + bias;
}

// ---------------------------------------------------------------------------
extern "C" void kernel_launch(void* const* d_in, const int* in_sizes, int n_in,
                              void* d_out, int out_size)
{
    const float* nf[2]  = { (const float*)d_in[0], (const float*)d_in[2] };
    const int*   src[2] = { (const int*)d_in[4],   (const int*)d_in[7] };
    const int*   dst[2] = { (const int*)d_in[5],   (const int*)d_in[8] };
    const int*   gid[2] = { (const int*)d_in[6],   (const int*)d_in[9] };
    const float* W[2]   = { (const float*)d_in[10], (const float*)d_in[14] };
    const float* b[2]   = { (const float*)d_in[11], (const float*)d_in[15] };
    const float* Wr[2]  = { (const float*)d_in[12], (const float*)d_in[16] };
    const float* br[2]  = { (const float*)d_in[13], (const float*)d_in[17] };
    const float* Ri[2]  = { (const float*)d_in[18], (const float*)d_in[22] };
    const float* rbi[2] = { (const float*)d_in[19], (const float*)d_in[23] };
    const float* Ro[2]  = { (const float*)d_in[20], (const float*)d_in[24] };
    const float* rbo[2] = { (const float*)d_in[21], (const float*)d_in[25] };
    const float* Wp = (const float*)d_in[26];
    const float* bp = (const float*)d_in[27];
    float* out = (float*)d_out;

    float *snode, *rowp;
    __half *hWp, *Rhp, *Ahp, *Alp, *Chp, *WtH;
    int *deg, *part, *rowptr, *woff, *bsum, *eidsrc;
    cudaGetSymbolAddress((void**)&hWp, g_hW);
    cudaGetSymbolAddress((void**)&Rhp, g_Rh);
    cudaGetSymbolAddress((void**)&Ahp, g_Ah);
    cudaGetSymbolAddress((void**)&Alp, g_Al);
    cudaGetSymbolAddress((void**)&Chp, g_Ch);
    cudaGetSymbolAddress((void**)&WtH, g_WtH);
    cudaGetSymbolAddress((void**)&snode, g_snode);
    cudaGetSymbolAddress((void**)&rowp, g_rowp);
    cudaGetSymbolAddress((void**)&deg, g_deg);
    cudaGetSymbolAddress((void**)&part, g_part);
    cudaGetSymbolAddress((void**)&rowptr, g_rowptr);
    cudaGetSymbolAddress((void**)&woff, g_woff);
    cudaGetSymbolAddress((void**)&bsum, g_bsum);
    cudaGetSymbolAddress((void**)&eidsrc, g_eidsrc);

    const size_t ND = (size_t)NN * DIM;

    cudaFuncSetAttribute((const void*)gemm_tc<M_HW,  true >, cudaFuncAttributeMaxDynamicSharedMemorySize, GEMM_SMEM);
    cudaFuncSetAttribute((const void*)gemm_tc<M_RES, false>, cudaFuncAttributeMaxDynamicSharedMemorySize, GEMM_SMEM);
    cudaFuncSetAttribute((const void*)gemm_tc<M_RD,  false>, cudaFuncAttributeMaxDynamicSharedMemorySize, GEMM_SMEM);

    const int n4 = NN * DIM / 4;
    const dim3 gridG(2, (NN + 127) / 128);

    // 1: weight transposes (fp16)
    wsplit_all<<<6 * 65536 / 256, 256>>>(W[0], Wr[0], Ri[0], W[1], Wr[1], Ri[1], WtH);
    // 2: zero snode + RoWp/rbowp precompute
    prep_zero_k<<<(2 * NN + 255) / 256, 256>>>(Ro[0], Ro[1], rbo[0], rbo[1], Wp, rowp, snode);
    // 3: split both h
    split2_k<<<(2 * n4 + 255) / 256, 256>>>((const float4*)nf[0], (const float4*)nf[1],
                                            (uint2*)Ahp, (uint2*)Alp,
                                            (uint2*)(Ahp + ND), (uint2*)(Alp + ND), n4);
    // 4: hW GEMM branch 0 (2-term)   [ncu-profiled slot]
    gemm_tc<M_HW, true><<<gridG, 256, GEMM_SMEM>>>(Ahp, Alp, WtH, nullptr, nullptr,
                                                   nullptr, hWp, NN);
    // 5: R GEMM branch 0 (1-term)
    gemm_tc<M_RES, false><<<gridG, 256, GEMM_SMEM>>>(Ahp, nullptr, WtH + 65536, br[0],
                                                     nullptr, nullptr, Rhp, NN);
    // 6-11: CSR build for BOTH branches
    zero2_i<<<(2 * NN + 255) / 256, 256>>>(deg, deg + NN, NN);
    hist2_k<<<(2 * NE + 255) / 256, 256>>>(dst[0], dst[1], deg, deg + NN, NE);
    scan1_k<<<2 * NB, 1024>>>(deg, part, bsum);
    scan2_k<<<1, 32>>>(bsum);
    scan3_k<<<2 * NB, 1024>>>(part, bsum, rowptr, woff);
    fill2_k<<<(2 * NE + 255) / 256, 256>>>(src[0], dst[0], src[1], dst[1],
                                           woff, woff + NN, eidsrc, eidsrc + NE, NE);
    // 12: gather+combine branch 0
    gather_combine_k<<<NN / 4, 128>>>((const uint4*)hWp, rowptr, eidsrc,
                                      (const uint4*)Rhp, b[0], (uint4*)Chp);
    // 13: readout GEMM branch 0 -> snode[0]
    gemm_tc<M_RD, false><<<gridG, 256, GEMM_SMEM>>>(Chp, nullptr, WtH + (size_t)2 * 65536,
                                                    rbi[0], rowp, snode, nullptr, NN);
    // 14: hW GEMM branch 1
    gemm_tc<M_HW, true><<<gridG, 256, GEMM_SMEM>>>(Ahp + ND, Alp + ND,
                                                   WtH + (size_t)3 * 65536, nullptr,
                                                   nullptr, nullptr, hWp, NN);
    // 15: R GEMM branch 1
    gemm_tc<M_RES, false><<<gridG, 256, GEMM_SMEM>>>(Ahp + ND, nullptr,
                                                     WtH + (size_t)4 * 65536, br[1],
                                                     nullptr, nullptr, Rhp, NN);
    // 16: gather+combine branch 1
    gather_combine_k<<<NN / 4, 128>>>((const uint4*)hWp, rowptr + NN + 1, eidsrc + NE,
                                      (const uint4*)Rhp, b[1], (uint4*)Chp);
    // 17: readout GEMM branch 1 -> snode[1] (RoWp slab offset 256)
    gemm_tc<M_RD, false><<<gridG, 256, GEMM_SMEM>>>(Chp, nullptr, WtH + (size_t)5 * 65536,
                                                    rbi[1], rowp + 256, snode + NN, nullptr, NN);
    // 18: final per-graph reduction + predictor
    final_k<<<(NG * 32 + 255) / 256, 256>>>(snode, gid[0], gid[1], rowp, bp, out);
}

// round 15
// speedup vs baseline: 1.5267x; 1.0992x over previous
#include <cuda_runtime.h>
#include <cuda_fp16.h>
#include <cstdint>

#define NN 50000
#define NE 800000
#define DIM 256
#define GF 200
#define NG 512

// ---------------------------------------------------------------------------
// Scratch (__device__ globals; no allocations allowed)
// ---------------------------------------------------------------------------
__device__ __half g_hW[(size_t)NN * DIM];        // hW (fp16)
__device__ __half g_Rh[(size_t)NN * DIM];        // relu(h@Wr+br) (fp16)
__device__ __half g_Hh[2][(size_t)NN * DIM];     // h (fp16, both branches)
__device__ __half g_Ch[(size_t)NN * DIM];        // h1 (fp16)
__device__ __half g_WtH[6 * DIM * DIM];          // transposed weights fp16
__device__ float g_snode[2][NN];                 // per-node readout scalars
__device__ float g_rowp[516];                    // RoWp0 | RoWp1 | rbo.Wp x2
// CSR scratch (both branches)
__device__ int g_deg[2][NN];
__device__ int g_part[2][NN];
__device__ int g_rowptr[2][NN + 1];
__device__ int g_woff[2][NN];
__device__ int g_bsum[2][64];
__device__ int g_eidsrc[2][NE];

enum { M_HW = 0, M_RES = 1, M_RD = 2 };

__device__ __forceinline__ float relu_f(float x) { return x > 0.f ? x : 0.f; }

__device__ __forceinline__ uint32_t smem_u32(const void* p) {
    uint32_t a;
    asm("{ .reg .u64 t; cvta.to.shared.u64 t, %1; cvt.u32.u64 %0, t; }" : "=r"(a) : "l"(p));
    return a;
}
__device__ __forceinline__ uint32_t swz(uint32_t off) { return off ^ ((off >> 3) & 0x70); }
__device__ __forceinline__ void cpa16(uint32_t s, const void* g, int sz) {
    asm volatile("cp.async.cg.shared.global [%0], [%1], 16, %2;" :: "r"(s), "l"(g), "r"(sz) : "memory");
}
__device__ __forceinline__ void ldsm4(uint32_t* r, uint32_t addr) {
    asm volatile("ldmatrix.sync.aligned.m8n8.x4.shared.b16 {%0,%1,%2,%3}, [%4];"
        : "=r"(r[0]), "=r"(r[1]), "=r"(r[2]), "=r"(r[3]) : "r"(addr));
}
__device__ __forceinline__ void mma16816(float* c, const uint32_t* a, const uint32_t* b) {
    asm volatile("mma.sync.aligned.m16n8k16.row.col.f32.f16.f16.f32 "
        "{%0,%1,%2,%3}, {%4,%5,%6,%7}, {%8,%9}, {%0,%1,%2,%3};"
        : "+f"(c[0]), "+f"(c[1]), "+f"(c[2]), "+f"(c[3])
        : "r"(a[0]), "r"(a[1]), "r"(a[2]), "r"(a[3]), "r"(b[0]), "r"(b[1]));
}

// ---------------------------------------------------------------------------
// HMMA GEMM: BM=128, BN=128, BK=64. 256 threads = 8 warps, warp tile 32x64.
// D = A*B, 1-term fp16. A/B smem double-buffered. 2 CTAs/SM.
// ---------------------------------------------------------------------------
static const int SM_A = 0;                 // 2buf x 16KB = 32KB
static const int SM_B = 32768;             // 2buf x 16KB = 32KB
static const int SM_BW = 66048;            // RD: rbi/rowp slices after f32 staging
static const int GEMM_SMEM = 67584;        // 66KB

template <int MODE>
__global__ __launch_bounds__(256, 2)
void gemm_tc(const __half* __restrict__ A,
             const __half* __restrict__ Bh,
             const float* __restrict__ bias,   // RES: br ; RD: rbi
             const float* __restrict__ rowp,   // RD: RoWp slab
             float* __restrict__ snode,        // RD
             __half* __restrict__ outH,        // HW: hW ; RES: R
             int M)
{
    extern __shared__ char smem_raw[];
    uint32_t sb = smem_u32(smem_raw);
    const int t = threadIdx.x;
    const int lane = t & 31;
    const int wid = t >> 5;
    const int rowBase = blockIdx.y * 128;
    const int colBase = blockIdx.x * 128;

    const int m0 = (wid & 3) * 32;
    const int n0 = (wid >> 2) * 64;

    const int ar = (lane & 7) + ((lane >> 3) & 1) * 8;
    const int ak = ((lane >> 4) & 1) * 8;
    const int br_ = (lane & 7) + ((lane >> 4) & 1) * 8;
    const int bk = ((lane >> 3) & 1) * 8;

    uint32_t aRel[2], bRel[4];
    #pragma unroll
    for (int mt = 0; mt < 2; mt++)
        aRel[mt] = swz((uint32_t)(m0 + mt * 16 + ar) * 128 + ak * 2);
    #pragma unroll
    for (int q = 0; q < 4; q++)
        bRel[q] = swz((uint32_t)(n0 + q * 16 + br_) * 128 + bk * 2);

    auto loadAB = [&](int c, int buf) {
        #pragma unroll
        for (int i = 0; i < 4; i++) {
            int idx = i * 256 + t;
            int row = idx >> 3, seg = idx & 7;
            int gr = rowBase + row;
            int ok = gr < M;
            uint32_t sa = sb + SM_A + buf * 16384 + swz(row * 128 + seg * 16);
            const __half* gp = A + (size_t)(ok ? gr : 0) * 256 + c * 64 + seg * 8;
            cpa16(sa, gp, ok ? 16 : 0);
        }
        #pragma unroll
        for (int i = 0; i < 4; i++) {
            int idx = i * 256 + t;
            int row = idx >> 3, seg = idx & 7;
            uint32_t sa = sb + SM_B + buf * 16384 + swz(row * 128 + seg * 16);
            const __half* gp = Bh + (size_t)(colBase + row) * 256 + c * 64 + seg * 8;
            cpa16(sa, gp, 16);
        }
    };
    loadAB(0, 0);
    asm volatile("cp.async.commit_group;" ::: "memory");

    float acc[2][8][4] = {};

    #pragma unroll
    for (int c = 0; c < 4; c++) {
        if (c < 3) {
            loadAB(c + 1, (c + 1) & 1);
            asm volatile("cp.async.commit_group;" ::: "memory");
            asm volatile("cp.async.wait_group 1;" ::: "memory");
        } else {
            asm volatile("cp.async.wait_group 0;" ::: "memory");
        }
        __syncthreads();

        uint32_t aB = sb + SM_A + (c & 1) * 16384;
        uint32_t bB = sb + SM_B + (c & 1) * 16384;

        #pragma unroll
        for (int kk2 = 0; kk2 < 128; kk2 += 32) {
            uint32_t ah[2][4], bh[4][4];
            #pragma unroll
            for (int mt = 0; mt < 2; mt++)
                ldsm4(ah[mt], aB + (aRel[mt] ^ kk2));
            #pragma unroll
            for (int q = 0; q < 4; q++)
                ldsm4(bh[q], bB + (bRel[q] ^ kk2));
            #pragma unroll
            for (int mt = 0; mt < 2; mt++)
                #pragma unroll
                for (int nt = 0; nt < 8; nt++)
                    mma16816(acc[mt][nt], ah[mt], &bh[nt >> 1][(nt & 1) * 2]);
        }
        __syncthreads();
    }

    if (MODE != M_RD) {
        __half* stg = (__half*)smem_raw;
        #pragma unroll
        for (int mt = 0; mt < 2; mt++) {
            #pragma unroll
            for (int nt = 0; nt < 8; nt++) {
                int r = m0 + mt * 16 + (lane >> 2);
                int cc = n0 + nt * 8 + (lane & 3) * 2;
                *(__half2*)&stg[r * 136 + cc] =
                    __floats2half2_rn(acc[mt][nt][0], acc[mt][nt][1]);
                *(__half2*)&stg[(r + 8) * 136 + cc] =
                    __floats2half2_rn(acc[mt][nt][2], acc[mt][nt][3]);
            }
        }
        __syncthreads();
        const int cl = t & 127;
        const int col = colBase + cl;
        if (MODE == M_HW) {
            for (int row = t >> 7; row < 128; row += 2) {
                int gr = rowBase + row;
                if (gr >= M) break;
                outH[(size_t)gr * 256 + col] = stg[row * 136 + cl];
            }
        } else {  // M_RES
            const float bc = bias[col];
            for (int row = t >> 7; row < 128; row += 2) {
                int gr = rowBase + row;
                if (gr >= M) break;
                float f = relu_f(__half2float(stg[row * 136 + cl]) + bc);
                outH[(size_t)gr * 256 + col] = __float2half_rn(f);
            }
        }
    } else {
        // RD: reduce each node row to a scalar: s = sum_c relu(t+rbi)*RoWp
        float* stg = (float*)smem_raw;
        float* sB = (float*)(smem_raw + SM_BW);        // rbi slice [128]
        float* sW = sB + 128;                          // RoWp slice [128]
        if (t < 128) sB[t] = bias[colBase + t];
        else sW[t - 128] = rowp[colBase + (t - 128)];
        #pragma unroll
        for (int mt = 0; mt < 2; mt++) {
            #pragma unroll
            for (int nt = 0; nt < 8; nt++) {
                int r = m0 + mt * 16 + (lane >> 2);
                int cc = n0 + nt * 8 + (lane & 3) * 2;
                stg[r * 129 + cc]           = acc[mt][nt][0];
                stg[r * 129 + cc + 1]       = acc[mt][nt][1];
                stg[(r + 8) * 129 + cc]     = acc[mt][nt][2];
                stg[(r + 8) * 129 + cc + 1] = acc[mt][nt][3];
            }
        }
        __syncthreads();
        const int row = t & 127;
        const int half = t >> 7;
        const int gr = rowBase + row;
        if (gr < M) {
            float s = 0.f;
            const int c0 = half * 64;
            #pragma unroll 8
            for (int c = c0; c < c0 + 64; c++)
                s += relu_f(stg[row * 129 + c] + sB[c]) * sW[c];
            atomicAdd(&snode[gr], s);
        }
    }
}

// ---------------------------------------------------------------------------
// fp32 -> fp16 convert, both branches in one launch
// ---------------------------------------------------------------------------
__global__ __launch_bounds__(256)
void conv2_k(const float4* __restrict__ in0, const float4* __restrict__ in1,
             uint2* __restrict__ H0, uint2* __restrict__ H1, int n4)
{
    int i = blockIdx.x * blockDim.x + threadIdx.x;
    const float4* in = in0; uint2* H = H0;
    if (i >= n4) { i -= n4; if (i >= n4) return; in = in1; H = H1; }
    float4 f = in[i];
    union { __half h[4]; uint2 u; } hh;
    hh.h[0] = __float2half_rn(f.x);
    hh.h[1] = __float2half_rn(f.y);
    hh.h[2] = __float2half_rn(f.z);
    hh.h[3] = __float2half_rn(f.w);
    H[i] = hh.u;
}

// All 6 weight transposes in one launch
__global__ __launch_bounds__(256)
void wsplit_all(const float* __restrict__ w0, const float* __restrict__ w1,
                const float* __restrict__ w2, const float* __restrict__ w3,
                const float* __restrict__ w4, const float* __restrict__ w5,
                __half* __restrict__ H)
{
    int idx = blockIdx.x * 256 + threadIdx.x;
    int m = idx >> 16;
    int rem = idx & 65535;
    int n = rem >> 8, k = rem & 255;
    const float* srcs[6] = { w0, w1, w2, w3, w4, w5 };
    H[idx] = __float2half_rn(srcs[m][k * DIM + n]);
}

// prep: zero snode (2*NN) + compute RoWp slabs + rbo.Wp scalars
__global__ __launch_bounds__(256)
void prep_zero_k(const float* __restrict__ Ro0, const float* __restrict__ Ro1,
                 const float* __restrict__ rbo0, const float* __restrict__ rbo1,
                 const float* __restrict__ Wp,
                 float* __restrict__ rowp, float* __restrict__ snode)
{
    int i = blockIdx.x * blockDim.x + threadIdx.x;
    if (i < 2 * NN) snode[i] = 0.f;
    if (i < 512) {
        const float* Ro = (i < 256) ? Ro0 : Ro1;
        int c = i & 255;
        float s = 0.f;
        for (int f = 0; f < GF; f++) s += Ro[c * GF + f] * Wp[f];
        rowp[i] = s;
    } else if (i == 512 || i == 513) {
        const float* rbo = (i == 512) ? rbo0 : rbo1;
        float s = 0.f;
        for (int f = 0; f < GF; f++) s += rbo[f] * Wp[f];
        rowp[i] = s;
    }
}

// ---------------------------------------------------------------------------
// CSR build — dual-branch, full parallelism
// ---------------------------------------------------------------------------
#define NB ((NN + 1023) / 1024)   // 49

__global__ void zero2_i(int* p0, int* p1, int n)
{
    int i = blockIdx.x * blockDim.x + threadIdx.x;
    if (i < n) p0[i] = 0;
    else if (i < 2 * n) p1[i - n] = 0;
}
__global__ __launch_bounds__(256)
void hist2_k(const int* __restrict__ d0, const int* __restrict__ d1,
             int* __restrict__ c0, int* __restrict__ c1, int n)
{
    int i = blockIdx.x * blockDim.x + threadIdx.x;
    if (i < n) atomicAdd(&c0[d0[i]], 1);
    else if (i < 2 * n) { i -= n; atomicAdd(&c1[d1[i]], 1); }
}
__global__ __launch_bounds__(1024)
void scan1_k(const int* __restrict__ deg, int* __restrict__ part, int* __restrict__ bsum)
{
    __shared__ int s[1024];
    int b = blockIdx.x / NB;
    int blk = blockIdx.x % NB;
    const int* dg = deg + (size_t)b * NN;
    int* pt = part + (size_t)b * NN;
    int t = threadIdx.x;
    int idx = blk * 1024 + t;
    int v = (idx < NN) ? dg[idx] : 0;
    s[t] = v;
    __syncthreads();
    #pragma unroll
    for (int off = 1; off < 1024; off <<= 1) {
        int x = (t >= off) ? s[t - off] : 0;
        __syncthreads();
        s[t] += x;
        __syncthreads();
    }
    if (idx < NN) pt[idx] = s[t] - v;
    if (t == 1023) bsum[b * 64 + blk] = s[1023];
}
__global__ void scan2_k(int* bsum)
{
    int b = threadIdx.x;
    if (b < 2) {
        int run = 0;
        for (int i = 0; i < NB; i++) { int v = bsum[b * 64 + i]; bsum[b * 64 + i] = run; run += v; }
    }
}
__global__ __launch_bounds__(1024)
void scan3_k(const int* __restrict__ part, const int* __restrict__ bsum,
             int* __restrict__ rowptr, int* __restrict__ woff)
{
    int b = blockIdx.x / NB;
    int blk = blockIdx.x % NB;
    int idx = blk * 1024 + threadIdx.x;
    const int* pt = part + (size_t)b * NN;
    int* rp = rowptr + (size_t)b * (NN + 1);
    int* wo = woff + (size_t)b * NN;
    if (idx < NN) {
        int r = pt[idx] + bsum[b * 64 + blk];
        rp[idx] = r;
        wo[idx] = r;
    }
    if (idx == 0) rp[NN] = NE;
}
__global__ __launch_bounds__(256)
void fill2_k(const int* __restrict__ s0, const int* __restrict__ d0,
             const int* __restrict__ s1, const int* __restrict__ d1,
             int* __restrict__ w0, int* __restrict__ w1,
             int* __restrict__ e0, int* __restrict__ e1, int n)
{
    int i = blockIdx.x * blockDim.x + threadIdx.x;
    if (i < n) {
        int pos = atomicAdd(&w0[d0[i]], 1);
        e0[pos] = s0[i];
    } else if (i < 2 * n) {
        i -= n;
        int pos = atomicAdd(&w1[d1[i]], 1);
        e1[pos] = s1[i];
    }
}

// ---------------------------------------------------------------------------
// Fused gather + combine: warp per node, uint4 (8 halfs) per lane.
// ---------------------------------------------------------------------------
__global__ __launch_bounds__(128)
void gather_combine_k(const uint4* __restrict__ hw4, const int* __restrict__ rowptr,
                      const int* __restrict__ eidsrc, const uint4* __restrict__ R4,
                      const float* __restrict__ bvec, uint4* __restrict__ Ch4)
{
    int node = blockIdx.x * 4 + (threadIdx.x >> 5);
    int lane = threadIdx.x & 31;
    int start = rowptr[node], end = rowptr[node + 1];
    float a[8] = {};
    int j = start;
    for (; j + 1 < end; j += 2) {
        int s0 = __ldg(eidsrc + j);
        int s1 = __ldg(eidsrc + j + 1);
        uint4 v0 = __ldg(hw4 + (size_t)s0 * 32 + lane);
        uint4 v1 = __ldg(hw4 + (size_t)s1 * 32 + lane);
        float2 f;
        f = __half22float2(*(__half2*)&v0.x); a[0] += f.x; a[1] += f.y;
        f = __half22float2(*(__half2*)&v0.y); a[2] += f.x; a[3] += f.y;
        f = __half22float2(*(__half2*)&v0.z); a[4] += f.x; a[5] += f.y;
        f = __half22float2(*(__half2*)&v0.w); a[6] += f.x; a[7] += f.y;
        f = __half22float2(*(__half2*)&v1.x); a[0] += f.x; a[1] += f.y;
        f = __half22float2(*(__half2*)&v1.y); a[2] += f.x; a[3] += f.y;
        f = __half22float2(*(__half2*)&v1.z); a[4] += f.x; a[5] += f.y;
        f = __half22float2(*(__half2*)&v1.w); a[6] += f.x; a[7] += f.y;
    }
    if (j < end) {
        int s0 = __ldg(eidsrc + j);
        uint4 v0 = __ldg(hw4 + (size_t)s0 * 32 + lane);
        float2 f;
        f = __half22float2(*(__half2*)&v0.x); a[0] += f.x; a[1] += f.y;
        f = __half22float2(*(__half2*)&v0.y); a[2] += f.x; a[3] += f.y;
        f = __half22float2(*(__half2*)&v0.z); a[4] += f.x; a[5] += f.y;
        f = __half22float2(*(__half2*)&v0.w); a[6] += f.x; a[7] += f.y;
    }
    uint4 rv = __ldg(R4 + (size_t)node * 32 + lane);
    const float4* b4 = (const float4*)bvec;
    float4 bb0 = b4[lane * 2], bb1 = b4[lane * 2 + 1];
    float2 r0 = __half22float2(*(__half2*)&rv.x);
    float2 r1 = __half22float2(*(__half2*)&rv.y);
    float2 r2 = __half22float2(*(__half2*)&rv.z);
    float2 r3 = __half22float2(*(__half2*)&rv.w);
    float v0 = relu_f(a[0] + bb0.x) + r0.x;
    float v1 = relu_f(a[1] + bb0.y) + r0.y;
    float v2 = relu_f(a[2] + bb0.z) + r1.x;
    float v3 = relu_f(a[3] + bb0.w) + r1.y;
    float v4 = relu_f(a[4] + bb1.x) + r2.x;
    float v5 = relu_f(a[5] + bb1.y) + r2.y;
    float v6 = relu_f(a[6] + bb1.z) + r3.x;
    float v7 = relu_f(a[7] + bb1.w) + r3.y;
    uint4 o;
    *(__half2*)&o.x = __floats2half2_rn(v0, v1);
    *(__half2*)&o.y = __floats2half2_rn(v2, v3);
    *(__half2*)&o.z = __floats2half2_rn(v4, v5);
    *(__half2*)&o.w = __floats2half2_rn(v6, v7);
    Ch4[(size_t)node * 32 + lane] = o;
}

// final: out[g] = segsum(snode0) + segsum(snode1) + cnt0*rbowp0 + cnt1*rbowp1 + bp
__global__ __launch_bounds__(256)
void final_k(const float* __restrict__ snode, const int* __restrict__ gid0,
             const int* __restrict__ gid1, const float* __restrict__ rowp,
             const float* __restrict__ bp, float* __restrict__ out)
{
    int warp = (int)((blockIdx.x * (size_t)blockDim.x + threadIdx.x) >> 5);
    int lane = threadIdx.x & 31;
    if (warp >= NG) return;
    int g = warp;
    float tot = 0.f;
    float bias = bp[0];
    #pragma unroll
    for (int k = 0; k < 2; k++) {
        const int* gid = k ? gid1 : gid0;
        const float* sn = snode + (size_t)k * NN;
        int lo = 0, hi = NN;
        while (lo < hi) { int m = (lo + hi) >> 1; if (gid[m] < g) lo = m + 1; else hi = m; }
        int lo2 = lo, hi2 = NN;
        while (lo2 < hi2) { int m = (lo2 + hi2) >> 1; if (gid[m] <= g) lo2 = m + 1; else hi2 = m; }
        bias += (float)(lo2 - lo) * rowp[512 + k];
        float s = 0.f;
        for (int i = lo + lane; i < lo2; i += 32) s += sn[i];
        tot += s;
    }
    #pragma unroll
    for (int o = 16; o; o >>= 1) tot += __shfl_xor_sync(0xffffffffu, tot, o);
    if (lane == 0) out[g] = tot + bias;
}

// ---------------------------------------------------------------------------
extern "C" void kernel_launch(void* const* d_in, const int* in_sizes, int n_in,
                              void* d_out, int out_size)
{
    const float* nf[2]  = { (const float*)d_in[0], (const float*)d_in[2] };
    const int*   src[2] = { (const int*)d_in[4],   (const int*)d_in[7] };
    const int*   dst[2] = { (const int*)d_in[5],   (const int*)d_in[8] };
    const int*   gid[2] = { (const int*)d_in[6],   (const int*)d_in[9] };
    const float* W[2]   = { (const float*)d_in[10], (const float*)d_in[14] };
    const float* b[2]   = { (const float*)d_in[11], (const float*)d_in[15] };
    const float* Wr[2]  = { (const float*)d_in[12], (const float*)d_in[16] };
    const float* br[2]  = { (const float*)d_in[13], (const float*)d_in[17] };
    const float* Ri[2]  = { (const float*)d_in[18], (const float*)d_in[22] };
    const float* rbi[2] = { (const float*)d_in[19], (const float*)d_in[23] };
    const float* Ro[2]  = { (const float*)d_in[20], (const float*)d_in[24] };
    const float* rbo[2] = { (const float*)d_in[21], (const float*)d_in[25] };
    const float* Wp = (const float*)d_in[26];
    const float* bp = (const float*)d_in[27];
    float* out = (float*)d_out;

    float *snode, *rowp;
    __half *hWp, *Rhp, *Hhp, *Chp, *WtH;
    int *deg, *part, *rowptr, *woff, *bsum, *eidsrc;
    cudaGetSymbolAddress((void**)&hWp, g_hW);
    cudaGetSymbolAddress((void**)&Rhp, g_Rh);
    cudaGetSymbolAddress((void**)&Hhp, g_Hh);
    cudaGetSymbolAddress((void**)&Chp, g_Ch);
    cudaGetSymbolAddress((void**)&WtH, g_WtH);
    cudaGetSymbolAddress((void**)&snode, g_snode);
    cudaGetSymbolAddress((void**)&rowp, g_rowp);
    cudaGetSymbolAddress((void**)&deg, g_deg);
    cudaGetSymbolAddress((void**)&part, g_part);
    cudaGetSymbolAddress((void**)&rowptr, g_rowptr);
    cudaGetSymbolAddress((void**)&woff, g_woff);
    cudaGetSymbolAddress((void**)&bsum, g_bsum);
    cudaGetSymbolAddress((void**)&eidsrc, g_eidsrc);

    const size_t ND = (size_t)NN * DIM;

    cudaFuncSetAttribute((const void*)gemm_tc<M_HW >, cudaFuncAttributeMaxDynamicSharedMemorySize, GEMM_SMEM);
    cudaFuncSetAttribute((const void*)gemm_tc<M_RES>, cudaFuncAttributeMaxDynamicSharedMemorySize, GEMM_SMEM);
    cudaFuncSetAttribute((const void*)gemm_tc<M_RD >, cudaFuncAttributeMaxDynamicSharedMemorySize, GEMM_SMEM);

    const int n4 = NN * DIM / 4;
    const dim3 gridG(2, (NN + 127) / 128);

    // 1: weight transposes (fp16)
    wsplit_all<<<6 * 65536 / 256, 256>>>(W[0], Wr[0], Ri[0], W[1], Wr[1], Ri[1], WtH);
    // 2: zero snode + RoWp/rbowp precompute
    prep_zero_k<<<(2 * NN + 255) / 256, 256>>>(Ro[0], Ro[1], rbo[0], rbo[1], Wp, rowp, snode);
    // 3: convert both h -> fp16
    conv2_k<<<(2 * n4 + 255) / 256, 256>>>((const float4*)nf[0], (const float4*)nf[1],
                                           (uint2*)Hhp, (uint2*)(Hhp + ND), n4);
    // 4: hW GEMM branch 0   [ncu-profiled slot]
    gemm_tc<M_HW><<<gridG, 256, GEMM_SMEM>>>(Hhp, WtH, nullptr, nullptr, nullptr, hWp, NN);
    // 5: R GEMM branch 0
    gemm_tc<M_RES><<<gridG, 256, GEMM_SMEM>>>(Hhp, WtH + 65536, br[0], nullptr, nullptr, Rhp, NN);
    // 6-11: CSR build for BOTH branches
    zero2_i<<<(2 * NN + 255) / 256, 256>>>(deg, deg + NN, NN);
    hist2_k<<<(2 * NE + 255) / 256, 256>>>(dst[0], dst[1], deg, deg + NN, NE);
    scan1_k<<<2 * NB, 1024>>>(deg, part, bsum);
    scan2_k<<<1, 32>>>(bsum);
    scan3_k<<<2 * NB, 1024>>>(part, bsum, rowptr, woff);
    fill2_k<<<(2 * NE + 255) / 256, 256>>>(src[0], dst[0], src[1], dst[1],
                                           woff, woff + NN, eidsrc, eidsrc + NE, NE);
    // 12: gather+combine branch 0
    gather_combine_k<<<NN / 4, 128>>>((const uint4*)hWp, rowptr, eidsrc,
                                      (const uint4*)Rhp, b[0], (uint4*)Chp);
    // 13: readout GEMM branch 0 -> snode[0]
    gemm_tc<M_RD><<<gridG, 256, GEMM_SMEM>>>(Chp, WtH + (size_t)2 * 65536,
                                             rbi[0], rowp, snode, nullptr, NN);
    // 14: hW GEMM branch 1
    gemm_tc<M_HW><<<gridG, 256, GEMM_SMEM>>>(Hhp + ND, WtH + (size_t)3 * 65536,
                                             nullptr, nullptr, nullptr, hWp, NN);
    // 15: R GEMM branch 1
    gemm_tc<M_RES><<<gridG, 256, GEMM_SMEM>>>(Hhp + ND, WtH + (size_t)4 * 65536, br[1],
                                              nullptr, nullptr, Rhp, NN);
    // 16: gather+combine branch 1
    gather_combine_k<<<NN / 4, 128>>>((const uint4*)hWp, rowptr + NN + 1, eidsrc + NE,
                                      (const uint4*)Rhp, b[1], (uint4*)Chp);
    // 17: readout GEMM branch 1 -> snode[1]
    gemm_tc<M_RD><<<gridG, 256, GEMM_SMEM>>>(Chp, WtH + (size_t)5 * 65536,
                                             rbi[1], rowp + 256, snode + NN, nullptr, NN);
    // 18: final per-graph reduction + predictor
    final_k<<<(NG * 32 + 255) / 256, 256>>>(snode, gid[0], gid[1], rowp, bp, out);
}

// round 16
// speedup vs baseline: 1.6847x; 1.1035x over previous
#include <cuda_runtime.h>
#include <cuda_fp16.h>
#include <cstdint>

#define NN 50000
#define NE 800000
#define DIM 256
#define GF 200
#define NG 512

// ---------------------------------------------------------------------------
// Scratch (__device__ globals; no allocations allowed)
// ---------------------------------------------------------------------------
__device__ __half g_hW[2][(size_t)NN * DIM];     // hW (fp16, both branches)
__device__ __half g_Rh[2][(size_t)NN * DIM];     // relu(h@Wr+br)
__device__ __half g_Hh[2][(size_t)NN * DIM];     // h (fp16)
__device__ __half g_Ch[2][(size_t)NN * DIM];     // h1 (fp16)
__device__ __half g_WtH[6 * DIM * DIM];          // transposed weights fp16
__device__ float g_snode[2][NN];                 // per-node readout scalars
__device__ float g_rowp[516];                    // RoWp0 | RoWp1 | rbo.Wp x2
// CSR scratch (both branches)
__device__ int g_deg[2][NN];
__device__ int g_part[2][NN];
__device__ int g_rowptr[2][NN + 1];
__device__ int g_woff[2][NN];
__device__ int g_bsum[2][64];
__device__ int g_eidsrc[2][NE];

enum { M_HW = 0, M_RES = 1, M_RD = 2 };

__device__ __forceinline__ float relu_f(float x) { return x > 0.f ? x : 0.f; }

__device__ __forceinline__ uint32_t smem_u32(const void* p) {
    uint32_t a;
    asm("{ .reg .u64 t; cvta.to.shared.u64 t, %1; cvt.u32.u64 %0, t; }" : "=r"(a) : "l"(p));
    return a;
}
__device__ __forceinline__ uint32_t swz(uint32_t off) { return off ^ ((off >> 3) & 0x70); }
__device__ __forceinline__ void cpa16(uint32_t s, const void* g, int sz) {
    asm volatile("cp.async.cg.shared.global [%0], [%1], 16, %2;" :: "r"(s), "l"(g), "r"(sz) : "memory");
}
__device__ __forceinline__ void ldsm4(uint32_t* r, uint32_t addr) {
    asm volatile("ldmatrix.sync.aligned.m8n8.x4.shared.b16 {%0,%1,%2,%3}, [%4];"
        : "=r"(r[0]), "=r"(r[1]), "=r"(r[2]), "=r"(r[3]) : "r"(addr));
}
__device__ __forceinline__ void mma16816(float* c, const uint32_t* a, const uint32_t* b) {
    asm volatile("mma.sync.aligned.m16n8k16.row.col.f32.f16.f16.f32 "
        "{%0,%1,%2,%3}, {%4,%5,%6,%7}, {%8,%9}, {%0,%1,%2,%3};"
        : "+f"(c[0]), "+f"(c[1]), "+f"(c[2]), "+f"(c[3])
        : "r"(a[0]), "r"(a[1]), "r"(a[2]), "r"(a[3]), "r"(b[0]), "r"(b[1]));
}

// ---------------------------------------------------------------------------
// GEMM core: BM=128, BN=128, BK=64. 256 threads = 8 warps, warp tile 32x64.
// 1-term fp16. A/B smem double-buffered. 2 CTAs/SM.
// ---------------------------------------------------------------------------
static const int SM_A = 0;                 // 2buf x 16KB = 32KB
static const int SM_B = 32768;             // 2buf x 16KB = 32KB
static const int SM_BW = 66048;            // RD: rbi/rowp slices after f32 staging
static const int GEMM_SMEM = 67584;        // 66KB

template <int MODE>
__device__ __forceinline__ void gemm_core(
    const __half* __restrict__ A, const __half* __restrict__ Bh,
    const float* __restrict__ bias,   // RES: br ; RD: rbi
    const float* __restrict__ rowp,   // RD
    float* __restrict__ snode,        // RD
    __half* __restrict__ outH,        // HW / RES
    int M, int rowBase, int colBase, char* smem_raw)
{
    uint32_t sb = smem_u32(smem_raw);
    const int t = threadIdx.x;
    const int lane = t & 31;
    const int wid = t >> 5;

    const int m0 = (wid & 3) * 32;
    const int n0 = (wid >> 2) * 64;

    const int ar = (lane & 7) + ((lane >> 3) & 1) * 8;
    const int ak = ((lane >> 4) & 1) * 8;
    const int br_ = (lane & 7) + ((lane >> 4) & 1) * 8;
    const int bk = ((lane >> 3) & 1) * 8;

    uint32_t aRel[2], bRel[4];
    #pragma unroll
    for (int mt = 0; mt < 2; mt++)
        aRel[mt] = swz((uint32_t)(m0 + mt * 16 + ar) * 128 + ak * 2);
    #pragma unroll
    for (int q = 0; q < 4; q++)
        bRel[q] = swz((uint32_t)(n0 + q * 16 + br_) * 128 + bk * 2);

    auto loadAB = [&](int c, int buf) {
        #pragma unroll
        for (int i = 0; i < 4; i++) {
            int idx = i * 256 + t;
            int row = idx >> 3, seg = idx & 7;
            int gr = rowBase + row;
            int ok = gr < M;
            uint32_t sa = sb + SM_A + buf * 16384 + swz(row * 128 + seg * 16);
            const __half* gp = A + (size_t)(ok ? gr : 0) * 256 + c * 64 + seg * 8;
            cpa16(sa, gp, ok ? 16 : 0);
        }
        #pragma unroll
        for (int i = 0; i < 4; i++) {
            int idx = i * 256 + t;
            int row = idx >> 3, seg = idx & 7;
            uint32_t sa = sb + SM_B + buf * 16384 + swz(row * 128 + seg * 16);
            const __half* gp = Bh + (size_t)(colBase + row) * 256 + c * 64 + seg * 8;
            cpa16(sa, gp, 16);
        }
    };
    loadAB(0, 0);
    asm volatile("cp.async.commit_group;" ::: "memory");

    float acc[2][8][4] = {};

    #pragma unroll
    for (int c = 0; c < 4; c++) {
        if (c < 3) {
            loadAB(c + 1, (c + 1) & 1);
            asm volatile("cp.async.commit_group;" ::: "memory");
            asm volatile("cp.async.wait_group 1;" ::: "memory");
        } else {
            asm volatile("cp.async.wait_group 0;" ::: "memory");
        }
        __syncthreads();

        uint32_t aB = sb + SM_A + (c & 1) * 16384;
        uint32_t bB = sb + SM_B + (c & 1) * 16384;

        #pragma unroll
        for (int kk2 = 0; kk2 < 128; kk2 += 32) {
            uint32_t ah[2][4], bh[4][4];
            #pragma unroll
            for (int mt = 0; mt < 2; mt++)
                ldsm4(ah[mt], aB + (aRel[mt] ^ kk2));
            #pragma unroll
            for (int q = 0; q < 4; q++)
                ldsm4(bh[q], bB + (bRel[q] ^ kk2));
            #pragma unroll
            for (int mt = 0; mt < 2; mt++)
                #pragma unroll
                for (int nt = 0; nt < 8; nt++)
                    mma16816(acc[mt][nt], ah[mt], &bh[nt >> 1][(nt & 1) * 2]);
        }
        __syncthreads();
    }

    if (MODE != M_RD) {
        __half* stg = (__half*)smem_raw;
        #pragma unroll
        for (int mt = 0; mt < 2; mt++) {
            #pragma unroll
            for (int nt = 0; nt < 8; nt++) {
                int r = m0 + mt * 16 + (lane >> 2);
                int cc = n0 + nt * 8 + (lane & 3) * 2;
                *(__half2*)&stg[r * 136 + cc] =
                    __floats2half2_rn(acc[mt][nt][0], acc[mt][nt][1]);
                *(__half2*)&stg[(r + 8) * 136 + cc] =
                    __floats2half2_rn(acc[mt][nt][2], acc[mt][nt][3]);
            }
        }
        __syncthreads();
        const int cl = t & 127;
        const int col = colBase + cl;
        if (MODE == M_HW) {
            for (int row = t >> 7; row < 128; row += 2) {
                int gr = rowBase + row;
                if (gr >= M) break;
                outH[(size_t)gr * 256 + col] = stg[row * 136 + cl];
            }
        } else {  // M_RES
            const float bc = bias[col];
            for (int row = t >> 7; row < 128; row += 2) {
                int gr = rowBase + row;
                if (gr >= M) break;
                float f = relu_f(__half2float(stg[row * 136 + cl]) + bc);
                outH[(size_t)gr * 256 + col] = __float2half_rn(f);
            }
        }
    } else {
        float* stg = (float*)smem_raw;
        float* sB = (float*)(smem_raw + SM_BW);
        float* sW = sB + 128;
        if (t < 128) sB[t] = bias[colBase + t];
        else sW[t - 128] = rowp[colBase + (t - 128)];
        #pragma unroll
        for (int mt = 0; mt < 2; mt++) {
            #pragma unroll
            for (int nt = 0; nt < 8; nt++) {
                int r = m0 + mt * 16 + (lane >> 2);
                int cc = n0 + nt * 8 + (lane & 3) * 2;
                stg[r * 129 + cc]           = acc[mt][nt][0];
                stg[r * 129 + cc + 1]       = acc[mt][nt][1];
                stg[(r + 8) * 129 + cc]     = acc[mt][nt][2];
                stg[(r + 8) * 129 + cc + 1] = acc[mt][nt][3];
            }
        }
        __syncthreads();
        const int row = t & 127;
        const int half = t >> 7;
        const int gr = rowBase + row;
        if (gr < M) {
            float s = 0.f;
            const int c0 = half * 64;
            #pragma unroll 8
            for (int c = c0; c < c0 + 64; c++)
                s += relu_f(stg[row * 129 + c] + sB[c]) * sW[c];
            atomicAdd(&snode[gr], s);
        }
    }
}

// Mega-launch: grid (4, 391, 3).
// z<2: branch z GEMMs — x<2: hW (B = W slab), x>=2: R (B = Wr slab).
// z==2: edge histogram for both branches (runs in GEMM tail slots).
__global__ __launch_bounds__(256, 2)
void hwres_hist(const __half* __restrict__ Hh, const __half* __restrict__ WtH,
                const float* __restrict__ br0, const float* __restrict__ br1,
                __half* __restrict__ hW, __half* __restrict__ Rh,
                const int* __restrict__ dst0, const int* __restrict__ dst1,
                int* __restrict__ deg)
{
    extern __shared__ char smem_raw[];
    const int z = blockIdx.z;
    if (z < 2) {
        const __half* A = Hh + (size_t)z * NN * DIM;
        int rowBase = blockIdx.y * 128;
        if (blockIdx.x < 2) {
            const __half* B = WtH + (size_t)(z * 3) * 65536;
            gemm_core<M_HW>(A, B, nullptr, nullptr, nullptr,
                            hW + (size_t)z * NN * DIM,
                            NN, rowBase, blockIdx.x * 128, smem_raw);
        } else {
            const __half* B = WtH + (size_t)(z * 3 + 1) * 65536;
            gemm_core<M_RES>(A, B, z ? br1 : br0, nullptr, nullptr,
                             Rh + (size_t)z * NN * DIM,
                             NN, rowBase, (blockIdx.x - 2) * 128, smem_raw);
        }
    } else {
        // histogram: 1564 CTAs cover 2*NE edges grid-stride
        int nC = gridDim.x * gridDim.y;                  // 1564
        int cta = blockIdx.y * gridDim.x + blockIdx.x;
        int stride = nC * 256;
        for (int i = cta * 256 + threadIdx.x; i < 2 * NE; i += stride) {
            if (i < NE) atomicAdd(&deg[dst0[i]], 1);
            else        atomicAdd(&deg[NN + dst1[i - NE]], 1);
        }
    }
}

// Merged readout GEMM: grid (2, 391, 2). z = branch.
__global__ __launch_bounds__(256, 2)
void gemm_rd2(const __half* __restrict__ Ch, const __half* __restrict__ WtH,
              const float* __restrict__ rbi0, const float* __restrict__ rbi1,
              const float* __restrict__ rowp, float* __restrict__ snode)
{
    extern __shared__ char smem_raw[];
    const int z = blockIdx.z;
    gemm_core<M_RD>(Ch + (size_t)z * NN * DIM,
                    WtH + (size_t)(z * 3 + 2) * 65536,
                    z ? rbi1 : rbi0, rowp + z * 256, snode + (size_t)z * NN,
                    nullptr, NN, blockIdx.y * 128, blockIdx.x * 128, smem_raw);
}

// ---------------------------------------------------------------------------
// fp32 -> fp16 convert, both branches
// ---------------------------------------------------------------------------
__global__ __launch_bounds__(256)
void conv2_k(const float4* __restrict__ in0, const float4* __restrict__ in1,
             uint2* __restrict__ H0, uint2* __restrict__ H1, int n4)
{
    int i = blockIdx.x * blockDim.x + threadIdx.x;
    const float4* in = in0; uint2* H = H0;
    if (i >= n4) { i -= n4; if (i >= n4) return; in = in1; H = H1; }
    float4 f = in[i];
    union { __half h[4]; uint2 u; } hh;
    hh.h[0] = __float2half_rn(f.x);
    hh.h[1] = __float2half_rn(f.y);
    hh.h[2] = __float2half_rn(f.z);
    hh.h[3] = __float2half_rn(f.w);
    H[i] = hh.u;
}

__global__ __launch_bounds__(256)
void wsplit_all(const float* __restrict__ w0, const float* __restrict__ w1,
                const float* __restrict__ w2, const float* __restrict__ w3,
                const float* __restrict__ w4, const float* __restrict__ w5,
                __half* __restrict__ H)
{
    int idx = blockIdx.x * 256 + threadIdx.x;
    int m = idx >> 16;
    int rem = idx & 65535;
    int n = rem >> 8, k = rem & 255;
    const float* srcs[6] = { w0, w1, w2, w3, w4, w5 };
    H[idx] = __float2half_rn(srcs[m][k * DIM + n]);
}

// prep: zero snode + zero deg (both 2*NN) + RoWp slabs + rbo.Wp
__global__ __launch_bounds__(256)
void prep_zero_k(const float* __restrict__ Ro0, const float* __restrict__ Ro1,
                 const float* __restrict__ rbo0, const float* __restrict__ rbo1,
                 const float* __restrict__ Wp,
                 float* __restrict__ rowp, float* __restrict__ snode,
                 int* __restrict__ deg)
{
    int i = blockIdx.x * blockDim.x + threadIdx.x;
    if (i < 2 * NN) { snode[i] = 0.f; deg[i] = 0; }
    if (i < 512) {
        const float* Ro = (i < 256) ? Ro0 : Ro1;
        int c = i & 255;
        float s = 0.f;
        for (int f = 0; f < GF; f++) s += Ro[c * GF + f] * Wp[f];
        rowp[i] = s;
    } else if (i == 512 || i == 513) {
        const float* rbo = (i == 512) ? rbo0 : rbo1;
        float s = 0.f;
        for (int f = 0; f < GF; f++) s += rbo[f] * Wp[f];
        rowp[i] = s;
    }
}

// ---------------------------------------------------------------------------
// CSR scan + fill — dual-branch
// ---------------------------------------------------------------------------
#define NB ((NN + 1023) / 1024)   // 49

__global__ __launch_bounds__(1024)
void scan1_k(const int* __restrict__ deg, int* __restrict__ part, int* __restrict__ bsum)
{
    __shared__ int s[1024];
    int b = blockIdx.x / NB;
    int blk = blockIdx.x % NB;
    const int* dg = deg + (size_t)b * NN;
    int* pt = part + (size_t)b * NN;
    int t = threadIdx.x;
    int idx = blk * 1024 + t;
    int v = (idx < NN) ? dg[idx] : 0;
    s[t] = v;
    __syncthreads();
    #pragma unroll
    for (int off = 1; off < 1024; off <<= 1) {
        int x = (t >= off) ? s[t - off] : 0;
        __syncthreads();
        s[t] += x;
        __syncthreads();
    }
    if (idx < NN) pt[idx] = s[t] - v;
    if (t == 1023) bsum[b * 64 + blk] = s[1023];
}
__global__ void scan2_k(int* bsum)
{
    int b = threadIdx.x;
    if (b < 2) {
        int run = 0;
        for (int i = 0; i < NB; i++) { int v = bsum[b * 64 + i]; bsum[b * 64 + i] = run; run += v; }
    }
}
__global__ __launch_bounds__(1024)
void scan3_k(const int* __restrict__ part, const int* __restrict__ bsum,
             int* __restrict__ rowptr, int* __restrict__ woff)
{
    int b = blockIdx.x / NB;
    int blk = blockIdx.x % NB;
    int idx = blk * 1024 + threadIdx.x;
    const int* pt = part + (size_t)b * NN;
    int* rp = rowptr + (size_t)b * (NN + 1);
    int* wo = woff + (size_t)b * NN;
    if (idx < NN) {
        int r = pt[idx] + bsum[b * 64 + blk];
        rp[idx] = r;
        wo[idx] = r;
    }
    if (idx == 0) rp[NN] = NE;
}
__global__ __launch_bounds__(256)
void fill2_k(const int* __restrict__ s0, const int* __restrict__ d0,
             const int* __restrict__ s1, const int* __restrict__ d1,
             int* __restrict__ w0, int* __restrict__ w1,
             int* __restrict__ e0, int* __restrict__ e1, int n)
{
    int i = blockIdx.x * blockDim.x + threadIdx.x;
    if (i < n) {
        int pos = atomicAdd(&w0[d0[i]], 1);
        e0[pos] = s0[i];
    } else if (i < 2 * n) {
        i -= n;
        int pos = atomicAdd(&w1[d1[i]], 1);
        e1[pos] = s1[i];
    }
}

// ---------------------------------------------------------------------------
// Fused gather + combine, both branches: grid (NN/4, 2). Warp per node.
// ---------------------------------------------------------------------------
__global__ __launch_bounds__(128)
void gather2_k(const uint4* __restrict__ hW, const int* __restrict__ rowptr,
               const int* __restrict__ eidsrc, const uint4* __restrict__ Rh,
               const float* __restrict__ b0, const float* __restrict__ b1,
               uint4* __restrict__ Ch)
{
    const int z = blockIdx.y;
    const uint4* hw4 = hW + (size_t)z * NN * 32;
    const uint4* R4 = Rh + (size_t)z * NN * 32;
    uint4* Ch4 = Ch + (size_t)z * NN * 32;
    const int* rp = rowptr + (size_t)z * (NN + 1);
    const int* es = eidsrc + (size_t)z * NE;
    const float* bvec = z ? b1 : b0;

    int node = blockIdx.x * 4 + (threadIdx.x >> 5);
    int lane = threadIdx.x & 31;
    int start = rp[node], end = rp[node + 1];
    float a[8] = {};
    int j = start;
    for (; j + 1 < end; j += 2) {
        int s0 = __ldg(es + j);
        int s1 = __ldg(es + j + 1);
        uint4 v0 = __ldg(hw4 + (size_t)s0 * 32 + lane);
        uint4 v1 = __ldg(hw4 + (size_t)s1 * 32 + lane);
        float2 f;
        f = __half22float2(*(__half2*)&v0.x); a[0] += f.x; a[1] += f.y;
        f = __half22float2(*(__half2*)&v0.y); a[2] += f.x; a[3] += f.y;
        f = __half22float2(*(__half2*)&v0.z); a[4] += f.x; a[5] += f.y;
        f = __half22float2(*(__half2*)&v0.w); a[6] += f.x; a[7] += f.y;
        f = __half22float2(*(__half2*)&v1.x); a[0] += f.x; a[1] += f.y;
        f = __half22float2(*(__half2*)&v1.y); a[2] += f.x; a[3] += f.y;
        f = __half22float2(*(__half2*)&v1.z); a[4] += f.x; a[5] += f.y;
        f = __half22float2(*(__half2*)&v1.w); a[6] += f.x; a[7] += f.y;
    }
    if (j < end) {
        int s0 = __ldg(es + j);
        uint4 v0 = __ldg(hw4 + (size_t)s0 * 32 + lane);
        float2 f;
        f = __half22float2(*(__half2*)&v0.x); a[0] += f.x; a[1] += f.y;
        f = __half22float2(*(__half2*)&v0.y); a[2] += f.x; a[3] += f.y;
        f = __half22float2(*(__half2*)&v0.z); a[4] += f.x; a[5] += f.y;
        f = __half22float2(*(__half2*)&v0.w); a[6] += f.x; a[7] += f.y;
    }
    uint4 rv = __ldg(R4 + (size_t)node * 32 + lane);
    const float4* b4 = (const float4*)bvec;
    float4 bb0 = b4[lane * 2], bb1 = b4[lane * 2 + 1];
    float2 r0 = __half22float2(*(__half2*)&rv.x);
    float2 r1 = __half22float2(*(__half2*)&rv.y);
    float2 r2 = __half22float2(*(__half2*)&rv.z);
    float2 r3 = __half22float2(*(__half2*)&rv.w);
    float v0 = relu_f(a[0] + bb0.x) + r0.x;
    float v1 = relu_f(a[1] + bb0.y) + r0.y;
    float v2 = relu_f(a[2] + bb0.z) + r1.x;
    float v3 = relu_f(a[3] + bb0.w) + r1.y;
    float v4 = relu_f(a[4] + bb1.x) + r2.x;
    float v5 = relu_f(a[5] + bb1.y) + r2.y;
    float v6 = relu_f(a[6] + bb1.z) + r3.x;
    float v7 = relu_f(a[7] + bb1.w) + r3.y;
    uint4 o;
    *(__half2*)&o.x = __floats2half2_rn(v0, v1);
    *(__half2*)&o.y = __floats2half2_rn(v2, v3);
    *(__half2*)&o.z = __floats2half2_rn(v4, v5);
    *(__half2*)&o.w = __floats2half2_rn(v6, v7);
    Ch4[(size_t)node * 32 + lane] = o;
}

// final: out[g] = segsum(snode0) + segsum(snode1) + cnt0*rbowp0 + cnt1*rbowp1 + bp
__global__ __launch_bounds__(256)
void final_k(const float* __restrict__ snode, const int* __restrict__ gid0,
             const int* __restrict__ gid1, const float* __restrict__ rowp,
             const float* __restrict__ bp, float* __restrict__ out)
{
    int warp = (int)((blockIdx.x * (size_t)blockDim.x + threadIdx.x) >> 5);
    int lane = threadIdx.x & 31;
    if (warp >= NG) return;
    int g = warp;
    float tot = 0.f;
    float bias = bp[0];
    #pragma unroll
    for (int k = 0; k < 2; k++) {
        const int* gid = k ? gid1 : gid0;
        const float* sn = snode + (size_t)k * NN;
        int lo = 0, hi = NN;
        while (lo < hi) { int m = (lo + hi) >> 1; if (gid[m] < g) lo = m + 1; else hi = m; }
        int lo2 = lo, hi2 = NN;
        while (lo2 < hi2) { int m = (lo2 + hi2) >> 1; if (gid[m] <= g) lo2 = m + 1; else hi2 = m; }
        bias += (float)(lo2 - lo) * rowp[512 + k];
        float s = 0.f;
        for (int i = lo + lane; i < lo2; i += 32) s += sn[i];
        tot += s;
    }
    #pragma unroll
    for (int o = 16; o; o >>= 1) tot += __shfl_xor_sync(0xffffffffu, tot, o);
    if (lane == 0) out[g] = tot + bias;
}

// ---------------------------------------------------------------------------
extern "C" void kernel_launch(void* const* d_in, const int* in_sizes, int n_in,
                              void* d_out, int out_size)
{
    const float* nf[2]  = { (const float*)d_in[0], (const float*)d_in[2] };
    const int*   src[2] = { (const int*)d_in[4],   (const int*)d_in[7] };
    const int*   dst[2] = { (const int*)d_in[5],   (const int*)d_in[8] };
    const int*   gid[2] = { (const int*)d_in[6],   (const int*)d_in[9] };
    const float* W[2]   = { (const float*)d_in[10], (const float*)d_in[14] };
    const float* b[2]   = { (const float*)d_in[11], (const float*)d_in[15] };
    const float* Wr[2]  = { (const float*)d_in[12], (const float*)d_in[16] };
    const float* br[2]  = { (const float*)d_in[13], (const float*)d_in[17] };
    const float* Ri[2]  = { (const float*)d_in[18], (const float*)d_in[22] };
    const float* rbi[2] = { (const float*)d_in[19], (const float*)d_in[23] };
    const float* Ro[2]  = { (const float*)d_in[20], (const float*)d_in[24] };
    const float* rbo[2] = { (const float*)d_in[21], (const float*)d_in[25] };
    const float* Wp = (const float*)d_in[26];
    const float* bp = (const float*)d_in[27];
    float* out = (float*)d_out;

    float *snode, *rowp;
    __half *hWp, *Rhp, *Hhp, *Chp, *WtH;
    int *deg, *part, *rowptr, *woff, *bsum, *eidsrc;
    cudaGetSymbolAddress((void**)&hWp, g_hW);
    cudaGetSymbolAddress((void**)&Rhp, g_Rh);
    cudaGetSymbolAddress((void**)&Hhp, g_Hh);
    cudaGetSymbolAddress((void**)&Chp, g_Ch);
    cudaGetSymbolAddress((void**)&WtH, g_WtH);
    cudaGetSymbolAddress((void**)&snode, g_snode);
    cudaGetSymbolAddress((void**)&rowp, g_rowp);
    cudaGetSymbolAddress((void**)&deg, g_deg);
    cudaGetSymbolAddress((void**)&part, g_part);
    cudaGetSymbolAddress((void**)&rowptr, g_rowptr);
    cudaGetSymbolAddress((void**)&woff, g_woff);
    cudaGetSymbolAddress((void**)&bsum, g_bsum);
    cudaGetSymbolAddress((void**)&eidsrc, g_eidsrc);

    const size_t ND = (size_t)NN * DIM;

    cudaFuncSetAttribute((const void*)hwres_hist, cudaFuncAttributeMaxDynamicSharedMemorySize, GEMM_SMEM);
    cudaFuncSetAttribute((const void*)gemm_rd2,   cudaFuncAttributeMaxDynamicSharedMemorySize, GEMM_SMEM);

    const int n4 = NN * DIM / 4;

    // 1: weight transposes (fp16)
    wsplit_all<<<6 * 65536 / 256, 256>>>(W[0], Wr[0], Ri[0], W[1], Wr[1], Ri[1], WtH);
    // 2: zero snode + deg, RoWp precompute
    prep_zero_k<<<(2 * NN + 255) / 256, 256>>>(Ro[0], Ro[1], rbo[0], rbo[1], Wp, rowp, snode, deg);
    // 3: convert both h -> fp16
    conv2_k<<<(2 * n4 + 255) / 256, 256>>>((const float4*)nf[0], (const float4*)nf[1],
                                           (uint2*)Hhp, (uint2*)(Hhp + ND), n4);
    // 4: mega GEMM (hW + R, both branches) + histogram in tail   [ncu slot]
    hwres_hist<<<dim3(4, (NN + 127) / 128, 3), 256, GEMM_SMEM>>>(
        Hhp, WtH, br[0], br[1], hWp, Rhp, dst[0], dst[1], deg);
    // 5-7: dual-branch scan
    scan1_k<<<2 * NB, 1024>>>(deg, part, bsum);
    scan2_k<<<1, 32>>>(bsum);
    scan3_k<<<2 * NB, 1024>>>(part, bsum, rowptr, woff);
    // 8: fill both CSRs
    fill2_k<<<(2 * NE + 255) / 256, 256>>>(src[0], dst[0], src[1], dst[1],
                                           woff, woff + NN, eidsrc, eidsrc + NE, NE);
    // 9: gather+combine both branches
    gather2_k<<<dim3(NN / 4, 2), 128>>>((const uint4*)hWp, rowptr, eidsrc,
                                        (const uint4*)Rhp, b[0], b[1], (uint4*)Chp);
    // 10: merged readout GEMM -> snode
    gemm_rd2<<<dim3(2, (NN + 127) / 128, 2), 256, GEMM_SMEM>>>(
        Chp, WtH, rbi[0], rbi[1], rowp, snode);
    // 11: final per-graph reduction + predictor
    final_k<<<(NG * 32 + 255) / 256, 256>>>(snode, gid[0], gid[1], rowp, bp, out);
}